// round 1
// baseline (speedup 1.0000x reference)
#include <cuda_runtime.h>
#include <math.h>

#define Bsz 128
#define Ssz 256
#define Hsz 384
#define NHs 12
#define DHs 32
#define Fsz 1536
#define Lyr 6
#define NOFF 5
#define ROWS (Bsz*Ssz)   /* 32768 */

// ---------------- scratch (static device globals; no allocation) --------------
__device__ float g_h[ROWS*Hsz];
__device__ float g_q[ROWS*Hsz];
__device__ float g_k[ROWS*Hsz];
__device__ float g_v[ROWS*Hsz];
__device__ float g_ctx[ROWS*Hsz];
__device__ float g_tmp[ROWS*Hsz];
__device__ float g_ff[ROWS*Fsz];
__device__ float g_pooled[Bsz*Hsz];
__device__ int   g_active[Bsz];
__device__ float g_scores[Bsz];
__device__ int   g_exitl[Bsz];

// ---------------- helpers ----------------------------------------------------
__device__ __forceinline__ float blockReduceSum128(float val, float* smem4) {
    int lane = threadIdx.x & 31, warp = threadIdx.x >> 5;
    #pragma unroll
    for (int o = 16; o > 0; o >>= 1) val += __shfl_down_sync(0xffffffffu, val, o);
    if (lane == 0) smem4[warp] = val;
    __syncthreads();
    float v = (threadIdx.x < 4) ? smem4[threadIdx.x] : 0.f;
    if (warp == 0) {
        v += __shfl_down_sync(0xffffffffu, v, 2);
        v += __shfl_down_sync(0xffffffffu, v, 1);
        if (lane == 0) smem4[0] = v;
    }
    __syncthreads();
    float r = smem4[0];
    __syncthreads();
    return r;
}

// ---------------- state init (must run every launch; graph replays) ----------
__global__ void init_state_kernel() {
    int t = threadIdx.x;
    if (t < Bsz) { g_active[t] = 1; g_scores[t] = 0.f; g_exitl[t] = 0; }
}

// ---------------- embeddings + LN --------------------------------------------
__global__ void embed_ln_kernel(const int* __restrict__ ids, const int* __restrict__ tts,
                                const float* __restrict__ we, const float* __restrict__ pe,
                                const float* __restrict__ te, const float* __restrict__ g,
                                const float* __restrict__ b) {
    __shared__ float red[4];
    int row = blockIdx.x, s = row & (Ssz - 1), tid = threadIdx.x;
    int id = ids[row], tt = tts[row];
    float x[3];
    #pragma unroll
    for (int i = 0; i < 3; i++) {
        int j = tid + i * 128;
        x[i] = we[id * Hsz + j] + pe[s * Hsz + j] + te[tt * Hsz + j];
    }
    float mean = blockReduceSum128(x[0] + x[1] + x[2], red) * (1.f / Hsz);
    float sq = 0.f;
    #pragma unroll
    for (int i = 0; i < 3; i++) { float d = x[i] - mean; sq += d * d; }
    float var = blockReduceSum128(sq, red) * (1.f / Hsz);
    float inv = rsqrtf(var + 1e-12f);
    #pragma unroll
    for (int i = 0; i < 3; i++) {
        int j = tid + i * 128;
        g_h[row * Hsz + j] = g[j] * (x[i] - mean) * inv + b[j];
    }
}

// ---------------- SGEMM: C = A[MxK] @ W[KxN] + bias, optional exact GELU ------
// 64x64 block tile, BK=16, 256 threads, 4x4 per-thread microtile.
__global__ void sgemm_kernel(const float* __restrict__ A, const float* __restrict__ W,
                             const float* __restrict__ bias, float* __restrict__ C,
                             int M, int N, int K, int act) {
    __shared__ float As[16][64];
    __shared__ float Bs[16][64];
    int t = threadIdx.x;
    int tx = t & 15, ty = t >> 4;
    int br = blockIdx.y * 64, bc = blockIdx.x * 64;
    float acc[4][4] = {};

    int arow = t >> 2, ac4 = (t & 3) * 4;       // A tile: 64 rows x 16 cols
    int brow = t >> 4, bc4 = (t & 15) * 4;      // B tile: 16 rows x 64 cols
    const float* Aptr = A + (size_t)(br + arow) * K + ac4;
    const float* Wptr = W + (size_t)brow * N + bc + bc4;

    for (int k0 = 0; k0 < K; k0 += 16) {
        float4 av = *reinterpret_cast<const float4*>(Aptr + k0);
        float4 wv = *reinterpret_cast<const float4*>(Wptr + (size_t)k0 * N);
        As[ac4 + 0][arow] = av.x; As[ac4 + 1][arow] = av.y;
        As[ac4 + 2][arow] = av.z; As[ac4 + 3][arow] = av.w;
        *reinterpret_cast<float4*>(&Bs[brow][bc4]) = wv;
        __syncthreads();
        #pragma unroll
        for (int kk = 0; kk < 16; kk++) {
            float a[4], w4[4];
            #pragma unroll
            for (int i = 0; i < 4; i++) a[i] = As[kk][ty * 4 + i];
            #pragma unroll
            for (int j = 0; j < 4; j++) w4[j] = Bs[kk][tx * 4 + j];
            #pragma unroll
            for (int i = 0; i < 4; i++)
                #pragma unroll
                for (int j = 0; j < 4; j++)
                    acc[i][j] = fmaf(a[i], w4[j], acc[i][j]);
        }
        __syncthreads();
    }
    #pragma unroll
    for (int i = 0; i < 4; i++) {
        int row = br + ty * 4 + i;
        float4 out;
        float* o = &out.x;
        #pragma unroll
        for (int j = 0; j < 4; j++) {
            int col = bc + tx * 4 + j;
            float v = acc[i][j] + bias[col];
            if (act == 1) v = 0.5f * v * (1.f + erff(v * 0.70710678118654752f));
            o[j] = v;
        }
        *reinterpret_cast<float4*>(&C[(size_t)row * N + bc + tx * 4]) = out;
    }
}

// ---------------- attention: one thread per query row, online softmax --------
__global__ void attn_kernel(const float* __restrict__ q, const float* __restrict__ k,
                            const float* __restrict__ v, const int* __restrict__ mask,
                            float* __restrict__ ctx) {
    __shared__ float Ks[128 * 32];
    __shared__ float Vs[128 * 32];
    __shared__ float bi[256];
    int head = blockIdx.x, b = blockIdx.y, tid = threadIdx.x;   // 256 threads
    bi[tid] = (1.f - (float)mask[b * Ssz + tid]) * -1e9f;

    float qr[32];
    const float* qp = q + (size_t)(b * Ssz + tid) * Hsz + head * DHs;
    #pragma unroll
    for (int d = 0; d < 32; d += 4) {
        float4 qq = *reinterpret_cast<const float4*>(qp + d);
        qr[d] = qq.x; qr[d + 1] = qq.y; qr[d + 2] = qq.z; qr[d + 3] = qq.w;
    }
    float m = -1e30f, l = 0.f, o[32];
    #pragma unroll
    for (int d = 0; d < 32; d++) o[d] = 0.f;

    for (int tile = 0; tile < 2; tile++) {
        int keybase = tile * 128;
        #pragma unroll
        for (int i = 0; i < 16; i++) {
            int e = tid + i * 256;
            int kj = e >> 5, kd = e & 31;
            size_t gidx = (size_t)(b * Ssz + keybase + kj) * Hsz + head * DHs + kd;
            Ks[e] = k[gidx];
            Vs[e] = v[gidx];
        }
        __syncthreads();
        for (int j = 0; j < 128; j++) {
            const float* kr = &Ks[j * 32];
            float s = 0.f;
            #pragma unroll
            for (int d = 0; d < 32; d++) s = fmaf(qr[d], kr[d], s);
            s = s * 0.17677669529663688f + bi[keybase + j];   // 1/sqrt(32)
            float mn = fmaxf(m, s);
            float corr = __expf(m - mn);
            float p = __expf(s - mn);
            l = l * corr + p;
            const float* vr = &Vs[j * 32];
            #pragma unroll
            for (int d = 0; d < 32; d++) o[d] = fmaf(o[d], corr, p * vr[d]);
            m = mn;
        }
        __syncthreads();
    }
    float invl = 1.f / l;
    float* cp = ctx + (size_t)(b * Ssz + tid) * Hsz + head * DHs;
    #pragma unroll
    for (int d = 0; d < 32; d++) cp[d] = o[d] * invl;
}

// ---------------- residual + LN: h = LN(h + delta) ---------------------------
__global__ void residual_ln_kernel(const float* __restrict__ delta,
                                   const float* __restrict__ g, const float* __restrict__ b) {
    __shared__ float red[4];
    int row = blockIdx.x, tid = threadIdx.x;
    float x[3];
    #pragma unroll
    for (int i = 0; i < 3; i++) {
        int j = tid + i * 128;
        x[i] = g_h[(size_t)row * Hsz + j] + delta[(size_t)row * Hsz + j];
    }
    float mean = blockReduceSum128(x[0] + x[1] + x[2], red) * (1.f / Hsz);
    float sq = 0.f;
    #pragma unroll
    for (int i = 0; i < 3; i++) { float d = x[i] - mean; sq += d * d; }
    float var = blockReduceSum128(sq, red) * (1.f / Hsz);
    float inv = rsqrtf(var + 1e-12f);
    #pragma unroll
    for (int i = 0; i < 3; i++) {
        int j = tid + i * 128;
        g_h[(size_t)row * Hsz + j] = g[j] * (x[i] - mean) * inv + b[j];
    }
}

// ---------------- offramp: entropy decision on CLS token ---------------------
__global__ void offramp_kernel(const float* __restrict__ Wr, const float* __restrict__ br,
                               int layer) {
    __shared__ float w[Hsz];
    int tid = threadIdx.x;  // 128
    #pragma unroll
    for (int i = 0; i < 3; i++) w[tid + i * 128] = Wr[layer * Hsz + tid + i * 128];
    __syncthreads();
    int b = tid;
    const float* hr = g_h + (size_t)(b * Ssz) * Hsz;
    float l = br[layer];
    for (int kk = 0; kk < Hsz; kk++) l = fmaf(hr[kk], w[kk], l);
    // stable log-sigmoid
    float lsp = (l > 0.f) ? -log1pf(expf(-l)) : (l - log1pf(expf(l)));    // log sig(l)
    float lsn = (l < 0.f) ? -log1pf(expf(l)) : (-l - log1pf(expf(-l)));   // log sig(-l)
    float p = 1.f / (1.f + expf(-l));
    float ent = -(p * lsp + (1.f - p) * lsn);
    if (g_active[b] && ent < 0.1f) {
        g_scores[b] = l; g_exitl[b] = layer; g_active[b] = 0;
    }
}

// ---------------- zero hidden rows of exited docs ----------------------------
__global__ void maskrows_kernel() {
    int row = blockIdx.x;
    int b = row >> 8;
    if (!g_active[b]) {
        int tid = threadIdx.x;
        #pragma unroll
        for (int i = 0; i < 3; i++) g_h[(size_t)row * Hsz + tid + i * 128] = 0.f;
    }
}

// ---------------- pooler: pooled = tanh(h[:,0,:] @ Wp + bp) -------------------
__global__ void pooler_kernel(const float* __restrict__ Wp, const float* __restrict__ bp) {
    __shared__ float hr[Hsz];
    int b = blockIdx.x, tid = threadIdx.x;   // 384 threads
    hr[tid] = g_h[(size_t)(b * Ssz) * Hsz + tid];
    __syncthreads();
    float acc = bp[tid];
    for (int kk = 0; kk < Hsz; kk++) acc = fmaf(hr[kk], Wp[kk * Hsz + tid], acc);
    g_pooled[b * Hsz + tid] = tanhf(acc);
}

// ---------------- final classifier + output assembly -------------------------
__global__ void final_kernel(const float* __restrict__ Wc, const float* __restrict__ bc,
                             float* __restrict__ out, int out_size) {
    __shared__ int counts[8];
    int tid = threadIdx.x;  // 128
    if (tid < 8) counts[tid] = 0;
    __syncthreads();
    int b = tid;
    float acc = bc[0];
    for (int kk = 0; kk < Hsz; kk++) acc = fmaf(g_pooled[b * Hsz + kk], Wc[kk], acc);
    float sc; int el;
    if (g_active[b]) { sc = acc; el = NOFF; }
    else             { sc = g_scores[b]; el = g_exitl[b]; }
    atomicAdd(&counts[el], 1);
    __syncthreads();
    out[b] = sc;
    out[Bsz + b] = (float)el;
    if (tid < NOFF + 1) out[2 * Bsz + tid] = (float)counts[tid];
    for (int i = 2 * Bsz + NOFF + 1 + tid; i < out_size; i += 128) out[i] = 0.f;
}

// ---------------- launch -----------------------------------------------------
extern "C" void kernel_launch(void* const* d_in, const int* in_sizes, int n_in,
                              void* d_out, int out_size) {
    (void)in_sizes; (void)n_in;
    const int*   input_ids      = (const int*)d_in[0];
    const int*   attention_mask = (const int*)d_in[1];
    const int*   token_type_ids = (const int*)d_in[2];
    const float* word_emb = (const float*)d_in[3];
    const float* pos_emb  = (const float*)d_in[4];
    const float* type_emb = (const float*)d_in[5];
    const float* emb_ln_g = (const float*)d_in[6];
    const float* emb_ln_b = (const float*)d_in[7];
    const float* Wq = (const float*)d_in[8];  const float* bq = (const float*)d_in[9];
    const float* Wk = (const float*)d_in[10]; const float* bk = (const float*)d_in[11];
    const float* Wv = (const float*)d_in[12]; const float* bv = (const float*)d_in[13];
    const float* Wo = (const float*)d_in[14]; const float* bo = (const float*)d_in[15];
    const float* ln1_g = (const float*)d_in[16]; const float* ln1_b = (const float*)d_in[17];
    const float* Wi = (const float*)d_in[18]; const float* bi = (const float*)d_in[19];
    const float* Wfo = (const float*)d_in[20]; const float* bfo = (const float*)d_in[21];
    const float* ln2_g = (const float*)d_in[22]; const float* ln2_b = (const float*)d_in[23];
    const float* Wp = (const float*)d_in[24]; const float* bp = (const float*)d_in[25];
    const float* Wc = (const float*)d_in[26]; const float* bc = (const float*)d_in[27];
    const float* Wr = (const float*)d_in[28]; const float* br = (const float*)d_in[29];

    float *hp, *qp, *kp, *vp, *cp, *tp, *fp;
    cudaGetSymbolAddress((void**)&hp, g_h);
    cudaGetSymbolAddress((void**)&qp, g_q);
    cudaGetSymbolAddress((void**)&kp, g_k);
    cudaGetSymbolAddress((void**)&vp, g_v);
    cudaGetSymbolAddress((void**)&cp, g_ctx);
    cudaGetSymbolAddress((void**)&tp, g_tmp);
    cudaGetSymbolAddress((void**)&fp, g_ff);

    init_state_kernel<<<1, 128>>>();
    embed_ln_kernel<<<ROWS, 128>>>(input_ids, token_type_ids, word_emb, pos_emb, type_emb,
                                   emb_ln_g, emb_ln_b);

    dim3 gHH(Hsz / 64, ROWS / 64);   // N=384 tiles
    dim3 gHF(Fsz / 64, ROWS / 64);   // N=1536 tiles

    for (int i = 0; i < Lyr; i++) {
        const float* wq = Wq + (size_t)i * Hsz * Hsz;
        const float* wk = Wk + (size_t)i * Hsz * Hsz;
        const float* wv = Wv + (size_t)i * Hsz * Hsz;
        const float* wo = Wo + (size_t)i * Hsz * Hsz;
        sgemm_kernel<<<gHH, 256>>>(hp, wq, bq + i * Hsz, qp, ROWS, Hsz, Hsz, 0);
        sgemm_kernel<<<gHH, 256>>>(hp, wk, bk + i * Hsz, kp, ROWS, Hsz, Hsz, 0);
        sgemm_kernel<<<gHH, 256>>>(hp, wv, bv + i * Hsz, vp, ROWS, Hsz, Hsz, 0);
        attn_kernel<<<dim3(NHs, Bsz), 256>>>(qp, kp, vp, attention_mask, cp);
        sgemm_kernel<<<gHH, 256>>>(cp, wo, bo + i * Hsz, tp, ROWS, Hsz, Hsz, 0);
        residual_ln_kernel<<<ROWS, 128>>>(tp, ln1_g + i * Hsz, ln1_b + i * Hsz);
        sgemm_kernel<<<gHF, 256>>>(hp, Wi + (size_t)i * Hsz * Fsz, bi + i * Fsz, fp,
                                   ROWS, Fsz, Hsz, 1);
        sgemm_kernel<<<gHH, 256>>>(fp, Wfo + (size_t)i * Fsz * Hsz, bfo + i * Hsz, tp,
                                   ROWS, Hsz, Fsz, 0);
        residual_ln_kernel<<<ROWS, 128>>>(tp, ln2_g + i * Hsz, ln2_b + i * Hsz);
        if (i < NOFF) {
            offramp_kernel<<<1, 128>>>(Wr, br, i);
            maskrows_kernel<<<ROWS, 128>>>();
        }
    }
    pooler_kernel<<<Bsz, Hsz>>>(Wp, bp);
    final_kernel<<<1, 128>>>(Wc, bc, (float*)d_out, out_size);
}

// round 2
// speedup vs baseline: 2.0226x; 2.0226x over previous
#include <cuda_runtime.h>
#include <math.h>

#define Bsz 128
#define Ssz 256
#define Hsz 384
#define NHs 12
#define DHs 32
#define Fsz 1536
#define Lyr 6
#define NOFF 5
#define ROWS (Bsz*Ssz)   /* 32768 */

// ---------------- scratch (static device globals; no allocation) --------------
__device__ float g_h[ROWS*Hsz];
__device__ float g_q[ROWS*Hsz];
__device__ float g_k[ROWS*Hsz];
__device__ float g_v[ROWS*Hsz];
__device__ float g_ctx[ROWS*Hsz];
__device__ float g_tmp[ROWS*Hsz];
__device__ float g_ff[ROWS*Fsz];
__device__ float g_pooled[Bsz*Hsz];
__device__ int   g_active[Bsz];
__device__ float g_scores[Bsz];
__device__ int   g_exitl[Bsz];

// ---------------- helpers ----------------------------------------------------
__device__ __forceinline__ float blockReduceSum128(float val, float* smem4) {
    int lane = threadIdx.x & 31, warp = threadIdx.x >> 5;
    #pragma unroll
    for (int o = 16; o > 0; o >>= 1) val += __shfl_down_sync(0xffffffffu, val, o);
    if (lane == 0) smem4[warp] = val;
    __syncthreads();
    float v = (threadIdx.x < 4) ? smem4[threadIdx.x] : 0.f;
    if (warp == 0) {
        v += __shfl_down_sync(0xffffffffu, v, 2);
        v += __shfl_down_sync(0xffffffffu, v, 1);
        if (lane == 0) smem4[0] = v;
    }
    __syncthreads();
    float r = smem4[0];
    __syncthreads();
    return r;
}

__device__ __forceinline__ unsigned f2tf32(float x) {
    unsigned r;
    asm("cvt.rna.tf32.f32 %0, %1;" : "=r"(r) : "f"(x));
    return r;
}

// ---------------- state init -------------------------------------------------
__global__ void init_state_kernel() {
    int t = threadIdx.x;
    if (t < Bsz) { g_active[t] = 1; g_scores[t] = 0.f; g_exitl[t] = 0; }
}

// ---------------- embeddings + LN --------------------------------------------
__global__ void embed_ln_kernel(const int* __restrict__ ids, const int* __restrict__ tts,
                                const float* __restrict__ we, const float* __restrict__ pe,
                                const float* __restrict__ te, const float* __restrict__ g,
                                const float* __restrict__ b) {
    __shared__ float red[4];
    int row = blockIdx.x, s = row & (Ssz - 1), tid = threadIdx.x;
    int id = ids[row], tt = tts[row];
    float x[3];
    #pragma unroll
    for (int i = 0; i < 3; i++) {
        int j = tid + i * 128;
        x[i] = we[id * Hsz + j] + pe[s * Hsz + j] + te[tt * Hsz + j];
    }
    float mean = blockReduceSum128(x[0] + x[1] + x[2], red) * (1.f / Hsz);
    float sq = 0.f;
    #pragma unroll
    for (int i = 0; i < 3; i++) { float d = x[i] - mean; sq += d * d; }
    float var = blockReduceSum128(sq, red) * (1.f / Hsz);
    float inv = rsqrtf(var + 1e-12f);
    #pragma unroll
    for (int i = 0; i < 3; i++) {
        int j = tid + i * 128;
        g_h[row * Hsz + j] = g[j] * (x[i] - mean) * inv + b[j];
    }
}

// ---------------- TF32 tensor-core GEMM --------------------------------------
// C[MxN] = A[MxK] @ W[KxN] + bias, optional exact GELU.
// 128x128 block tile, BK=16, 256 threads (8 warps as 2x4), warp tile 64x32,
// mma.sync.aligned.m16n8k8.row.col.f32.tf32.tf32.f32
__global__ __launch_bounds__(256) void tgemm_kernel(
        const float* __restrict__ A, const float* __restrict__ W,
        const float* __restrict__ bias, float* __restrict__ C,
        int M, int N, int K, int act) {
    __shared__ unsigned As[16][132];   // [k][m], pad 4 -> 2-way max conflicts
    __shared__ unsigned Bs[16][132];   // [k][n]

    const int t = threadIdx.x;
    const int lane = t & 31, warp = t >> 5;
    const int kk = lane & 3, r = lane >> 2;
    const int mw = (warp >> 2) * 64;       // warp m-offset within block (0/64)
    const int nw = (warp & 3) * 32;        // warp n-offset within block (0..96)
    const int br = blockIdx.y * 128, bc = blockIdx.x * 128;

    // global load indexing
    const int arow = t >> 2, ac4 = (t & 3) * 4;          // A: [128][16] tile
    const int brow = t >> 5, bc4 = (t & 31) * 4;         // B: [16][128] tile
    const float* Ap0 = A + (size_t)(br + arow) * K + ac4;
    const float* Ap1 = A + (size_t)(br + arow + 64) * K + ac4;
    const float* Wp0 = W + (size_t)brow * N + bc + bc4;
    const float* Wp1 = W + (size_t)(brow + 8) * N + bc + bc4;

    float acc[4][4][4];
    #pragma unroll
    for (int i = 0; i < 4; i++)
        #pragma unroll
        for (int j = 0; j < 4; j++)
            #pragma unroll
            for (int c = 0; c < 4; c++) acc[i][j][c] = 0.f;

    const int T = K >> 4;
    float4 av0 = *reinterpret_cast<const float4*>(Ap0);
    float4 av1 = *reinterpret_cast<const float4*>(Ap1);
    float4 wv0 = *reinterpret_cast<const float4*>(Wp0);
    float4 wv1 = *reinterpret_cast<const float4*>(Wp1);

    for (int tt = 0; tt < T; tt++) {
        // stage regs -> smem (with tf32 rounding)
        As[ac4 + 0][arow] = f2tf32(av0.x); As[ac4 + 1][arow] = f2tf32(av0.y);
        As[ac4 + 2][arow] = f2tf32(av0.z); As[ac4 + 3][arow] = f2tf32(av0.w);
        As[ac4 + 0][arow + 64] = f2tf32(av1.x); As[ac4 + 1][arow + 64] = f2tf32(av1.y);
        As[ac4 + 2][arow + 64] = f2tf32(av1.z); As[ac4 + 3][arow + 64] = f2tf32(av1.w);
        {
            uint4 u0, u1;
            u0.x = f2tf32(wv0.x); u0.y = f2tf32(wv0.y); u0.z = f2tf32(wv0.z); u0.w = f2tf32(wv0.w);
            u1.x = f2tf32(wv1.x); u1.y = f2tf32(wv1.y); u1.z = f2tf32(wv1.z); u1.w = f2tf32(wv1.w);
            *reinterpret_cast<uint4*>(&Bs[brow][bc4]) = u0;
            *reinterpret_cast<uint4*>(&Bs[brow + 8][bc4]) = u1;
        }
        __syncthreads();

        // prefetch next tile
        if (tt + 1 < T) {
            int k0 = (tt + 1) << 4;
            av0 = *reinterpret_cast<const float4*>(Ap0 + k0);
            av1 = *reinterpret_cast<const float4*>(Ap1 + k0);
            wv0 = *reinterpret_cast<const float4*>(Wp0 + (size_t)k0 * N);
            wv1 = *reinterpret_cast<const float4*>(Wp1 + (size_t)k0 * N);
        }

        // compute: 2 k-steps of 8
        #pragma unroll
        for (int ks = 0; ks < 16; ks += 8) {
            unsigned a[4][4], b[4][2];
            #pragma unroll
            for (int mt = 0; mt < 4; mt++) {
                int m = mw + mt * 16 + r;
                a[mt][0] = As[ks + kk][m];
                a[mt][1] = As[ks + kk][m + 8];
                a[mt][2] = As[ks + 4 + kk][m];
                a[mt][3] = As[ks + 4 + kk][m + 8];
            }
            #pragma unroll
            for (int nt = 0; nt < 4; nt++) {
                int n = nw + nt * 8 + r;
                b[nt][0] = Bs[ks + kk][n];
                b[nt][1] = Bs[ks + 4 + kk][n];
            }
            #pragma unroll
            for (int mt = 0; mt < 4; mt++)
                #pragma unroll
                for (int nt = 0; nt < 4; nt++) {
                    asm volatile(
                        "mma.sync.aligned.m16n8k8.row.col.f32.tf32.tf32.f32 "
                        "{%0,%1,%2,%3}, {%4,%5,%6,%7}, {%8,%9}, {%0,%1,%2,%3};"
                        : "+f"(acc[mt][nt][0]), "+f"(acc[mt][nt][1]),
                          "+f"(acc[mt][nt][2]), "+f"(acc[mt][nt][3])
                        : "r"(a[mt][0]), "r"(a[mt][1]), "r"(a[mt][2]), "r"(a[mt][3]),
                          "r"(b[nt][0]), "r"(b[nt][1]));
                }
        }
        __syncthreads();
    }

    // epilogue: bias (+ exact GELU), float2 stores
    #pragma unroll
    for (int nt = 0; nt < 4; nt++) {
        int col = bc + nw + nt * 8 + 2 * kk;
        float b0 = bias[col], b1 = bias[col + 1];
        #pragma unroll
        for (int mt = 0; mt < 4; mt++) {
            int row = br + mw + mt * 16 + r;
            float v0 = acc[mt][nt][0] + b0, v1 = acc[mt][nt][1] + b1;
            float v2 = acc[mt][nt][2] + b0, v3 = acc[mt][nt][3] + b1;
            if (act == 1) {
                v0 = 0.5f * v0 * (1.f + erff(v0 * 0.70710678118654752f));
                v1 = 0.5f * v1 * (1.f + erff(v1 * 0.70710678118654752f));
                v2 = 0.5f * v2 * (1.f + erff(v2 * 0.70710678118654752f));
                v3 = 0.5f * v3 * (1.f + erff(v3 * 0.70710678118654752f));
            }
            *reinterpret_cast<float2*>(&C[(size_t)row * N + col]) = make_float2(v0, v1);
            *reinterpret_cast<float2*>(&C[(size_t)(row + 8) * N + col]) = make_float2(v2, v3);
        }
    }
}

// ---------------- attention: one thread per query row, online softmax --------
__global__ void attn_kernel(const float* __restrict__ q, const float* __restrict__ k,
                            const float* __restrict__ v, const int* __restrict__ mask,
                            float* __restrict__ ctx) {
    __shared__ float Ks[128 * 32];
    __shared__ float Vs[128 * 32];
    __shared__ float bi[256];
    int head = blockIdx.x, b = blockIdx.y, tid = threadIdx.x;   // 256 threads
    bi[tid] = (1.f - (float)mask[b * Ssz + tid]) * -1e9f;

    float qr[32];
    const float* qp = q + (size_t)(b * Ssz + tid) * Hsz + head * DHs;
    #pragma unroll
    for (int d = 0; d < 32; d += 4) {
        float4 qq = *reinterpret_cast<const float4*>(qp + d);
        qr[d] = qq.x; qr[d + 1] = qq.y; qr[d + 2] = qq.z; qr[d + 3] = qq.w;
    }
    float m = -1e30f, l = 0.f, o[32];
    #pragma unroll
    for (int d = 0; d < 32; d++) o[d] = 0.f;

    for (int tile = 0; tile < 2; tile++) {
        int keybase = tile * 128;
        #pragma unroll
        for (int i = 0; i < 16; i++) {
            int e = tid + i * 256;
            int kj = e >> 5, kd = e & 31;
            size_t gidx = (size_t)(b * Ssz + keybase + kj) * Hsz + head * DHs + kd;
            Ks[e] = k[gidx];
            Vs[e] = v[gidx];
        }
        __syncthreads();
        for (int j = 0; j < 128; j++) {
            const float* kr = &Ks[j * 32];
            float s = 0.f;
            #pragma unroll
            for (int d = 0; d < 32; d++) s = fmaf(qr[d], kr[d], s);
            s = s * 0.17677669529663688f + bi[keybase + j];   // 1/sqrt(32)
            float mn = fmaxf(m, s);
            float corr = __expf(m - mn);
            float p = __expf(s - mn);
            l = l * corr + p;
            const float* vr = &Vs[j * 32];
            #pragma unroll
            for (int d = 0; d < 32; d++) o[d] = fmaf(o[d], corr, p * vr[d]);
            m = mn;
        }
        __syncthreads();
    }
    float invl = 1.f / l;
    float* cp = ctx + (size_t)(b * Ssz + tid) * Hsz + head * DHs;
    #pragma unroll
    for (int d = 0; d < 32; d++) cp[d] = o[d] * invl;
}

// ---------------- residual + LN: h = LN(h + delta) ---------------------------
__global__ void residual_ln_kernel(const float* __restrict__ delta,
                                   const float* __restrict__ g, const float* __restrict__ b) {
    __shared__ float red[4];
    int row = blockIdx.x, tid = threadIdx.x;
    float x[3];
    #pragma unroll
    for (int i = 0; i < 3; i++) {
        int j = tid + i * 128;
        x[i] = g_h[(size_t)row * Hsz + j] + delta[(size_t)row * Hsz + j];
    }
    float mean = blockReduceSum128(x[0] + x[1] + x[2], red) * (1.f / Hsz);
    float sq = 0.f;
    #pragma unroll
    for (int i = 0; i < 3; i++) { float d = x[i] - mean; sq += d * d; }
    float var = blockReduceSum128(sq, red) * (1.f / Hsz);
    float inv = rsqrtf(var + 1e-12f);
    #pragma unroll
    for (int i = 0; i < 3; i++) {
        int j = tid + i * 128;
        g_h[(size_t)row * Hsz + j] = g[j] * (x[i] - mean) * inv + b[j];
    }
}

// ---------------- offramp: entropy decision on CLS token ---------------------
__global__ void offramp_kernel(const float* __restrict__ Wr, const float* __restrict__ br,
                               int layer) {
    __shared__ float w[Hsz];
    int tid = threadIdx.x;  // 128
    #pragma unroll
    for (int i = 0; i < 3; i++) w[tid + i * 128] = Wr[layer * Hsz + tid + i * 128];
    __syncthreads();
    int b = tid;
    const float* hr = g_h + (size_t)(b * Ssz) * Hsz;
    float l = br[layer];
    for (int kk = 0; kk < Hsz; kk++) l = fmaf(hr[kk], w[kk], l);
    float lsp = (l > 0.f) ? -log1pf(expf(-l)) : (l - log1pf(expf(l)));
    float lsn = (l < 0.f) ? -log1pf(expf(l)) : (-l - log1pf(expf(-l)));
    float p = 1.f / (1.f + expf(-l));
    float ent = -(p * lsp + (1.f - p) * lsn);
    if (g_active[b] && ent < 0.1f) {
        g_scores[b] = l; g_exitl[b] = layer; g_active[b] = 0;
    }
}

// ---------------- zero hidden rows of exited docs ----------------------------
__global__ void maskrows_kernel() {
    int row = blockIdx.x;
    int b = row >> 8;
    if (!g_active[b]) {
        int tid = threadIdx.x;
        #pragma unroll
        for (int i = 0; i < 3; i++) g_h[(size_t)row * Hsz + tid + i * 128] = 0.f;
    }
}

// ---------------- pooler -----------------------------------------------------
__global__ void pooler_kernel(const float* __restrict__ Wp, const float* __restrict__ bp) {
    __shared__ float hr[Hsz];
    int b = blockIdx.x, tid = threadIdx.x;   // 384 threads
    hr[tid] = g_h[(size_t)(b * Ssz) * Hsz + tid];
    __syncthreads();
    float acc = bp[tid];
    for (int kk = 0; kk < Hsz; kk++) acc = fmaf(hr[kk], Wp[kk * Hsz + tid], acc);
    g_pooled[b * Hsz + tid] = tanhf(acc);
}

// ---------------- final classifier + output assembly -------------------------
__global__ void final_kernel(const float* __restrict__ Wc, const float* __restrict__ bc,
                             float* __restrict__ out, int out_size) {
    __shared__ int counts[8];
    int tid = threadIdx.x;  // 128
    if (tid < 8) counts[tid] = 0;
    __syncthreads();
    int b = tid;
    float acc = bc[0];
    for (int kk = 0; kk < Hsz; kk++) acc = fmaf(g_pooled[b * Hsz + kk], Wc[kk], acc);
    float sc; int el;
    if (g_active[b]) { sc = acc; el = NOFF; }
    else             { sc = g_scores[b]; el = g_exitl[b]; }
    atomicAdd(&counts[el], 1);
    __syncthreads();
    out[b] = sc;
    out[Bsz + b] = (float)el;
    if (tid < NOFF + 1) out[2 * Bsz + tid] = (float)counts[tid];
    for (int i = 2 * Bsz + NOFF + 1 + tid; i < out_size; i += 128) out[i] = 0.f;
}

// ---------------- launch -----------------------------------------------------
extern "C" void kernel_launch(void* const* d_in, const int* in_sizes, int n_in,
                              void* d_out, int out_size) {
    (void)in_sizes; (void)n_in;
    const int*   input_ids      = (const int*)d_in[0];
    const int*   attention_mask = (const int*)d_in[1];
    const int*   token_type_ids = (const int*)d_in[2];
    const float* word_emb = (const float*)d_in[3];
    const float* pos_emb  = (const float*)d_in[4];
    const float* type_emb = (const float*)d_in[5];
    const float* emb_ln_g = (const float*)d_in[6];
    const float* emb_ln_b = (const float*)d_in[7];
    const float* Wq = (const float*)d_in[8];  const float* bq = (const float*)d_in[9];
    const float* Wk = (const float*)d_in[10]; const float* bk = (const float*)d_in[11];
    const float* Wv = (const float*)d_in[12]; const float* bv = (const float*)d_in[13];
    const float* Wo = (const float*)d_in[14]; const float* bo = (const float*)d_in[15];
    const float* ln1_g = (const float*)d_in[16]; const float* ln1_b = (const float*)d_in[17];
    const float* Wi = (const float*)d_in[18]; const float* bi = (const float*)d_in[19];
    const float* Wfo = (const float*)d_in[20]; const float* bfo = (const float*)d_in[21];
    const float* ln2_g = (const float*)d_in[22]; const float* ln2_b = (const float*)d_in[23];
    const float* Wp = (const float*)d_in[24]; const float* bp = (const float*)d_in[25];
    const float* Wc = (const float*)d_in[26]; const float* bc = (const float*)d_in[27];
    const float* Wr = (const float*)d_in[28]; const float* br = (const float*)d_in[29];

    float *hp, *qp, *kp, *vp, *cp, *tp, *fp;
    cudaGetSymbolAddress((void**)&hp, g_h);
    cudaGetSymbolAddress((void**)&qp, g_q);
    cudaGetSymbolAddress((void**)&kp, g_k);
    cudaGetSymbolAddress((void**)&vp, g_v);
    cudaGetSymbolAddress((void**)&cp, g_ctx);
    cudaGetSymbolAddress((void**)&tp, g_tmp);
    cudaGetSymbolAddress((void**)&fp, g_ff);

    init_state_kernel<<<1, 128>>>();
    embed_ln_kernel<<<ROWS, 128>>>(input_ids, token_type_ids, word_emb, pos_emb, type_emb,
                                   emb_ln_g, emb_ln_b);

    dim3 gHH(Hsz / 128, ROWS / 128);   // (3, 256)
    dim3 gHF(Fsz / 128, ROWS / 128);   // (12, 256)

    for (int i = 0; i < Lyr; i++) {
        const float* wq = Wq + (size_t)i * Hsz * Hsz;
        const float* wk = Wk + (size_t)i * Hsz * Hsz;
        const float* wv = Wv + (size_t)i * Hsz * Hsz;
        const float* wo = Wo + (size_t)i * Hsz * Hsz;
        tgemm_kernel<<<gHH, 256>>>(hp, wq, bq + i * Hsz, qp, ROWS, Hsz, Hsz, 0);
        tgemm_kernel<<<gHH, 256>>>(hp, wk, bk + i * Hsz, kp, ROWS, Hsz, Hsz, 0);
        tgemm_kernel<<<gHH, 256>>>(hp, wv, bv + i * Hsz, vp, ROWS, Hsz, Hsz, 0);
        attn_kernel<<<dim3(NHs, Bsz), 256>>>(qp, kp, vp, attention_mask, cp);
        tgemm_kernel<<<gHH, 256>>>(cp, wo, bo + i * Hsz, tp, ROWS, Hsz, Hsz, 0);
        residual_ln_kernel<<<ROWS, 128>>>(tp, ln1_g + i * Hsz, ln1_b + i * Hsz);
        tgemm_kernel<<<gHF, 256>>>(hp, Wi + (size_t)i * Hsz * Fsz, bi + i * Fsz, fp,
                                   ROWS, Fsz, Hsz, 1);
        tgemm_kernel<<<gHH, 256>>>(fp, Wfo + (size_t)i * Fsz * Hsz, bfo + i * Hsz, tp,
                                   ROWS, Hsz, Fsz, 0);
        residual_ln_kernel<<<ROWS, 128>>>(tp, ln2_g + i * Hsz, ln2_b + i * Hsz);
        if (i < NOFF) {
            offramp_kernel<<<1, 128>>>(Wr, br, i);
            maskrows_kernel<<<ROWS, 128>>>();
        }
    }
    pooler_kernel<<<Bsz, Hsz>>>(Wp, bp);
    final_kernel<<<1, 128>>>(Wc, bc, (float*)d_out, out_size);
}

// round 4
// speedup vs baseline: 2.6118x; 1.2913x over previous
#include <cuda_runtime.h>
#include <math.h>

#define Bsz 128
#define Ssz 256
#define Hsz 384
#define NHs 12
#define DHs 32
#define Fsz 1536
#define Lyr 6
#define NOFF 5
#define ROWS (Bsz*Ssz)   /* 32768 */

// ---------------- scratch (static device globals; no allocation) --------------
__device__ float g_h[ROWS*Hsz];
__device__ float g_q[ROWS*Hsz];
__device__ float g_k[ROWS*Hsz];
__device__ float g_v[ROWS*Hsz];
__device__ float g_ctx[ROWS*Hsz];
__device__ float g_tmp[ROWS*Hsz];
__device__ float g_ff[ROWS*Fsz];
__device__ float g_pooled[Bsz*Hsz];
__device__ int   g_active[Bsz];
__device__ float g_scores[Bsz];
__device__ int   g_exitl[Bsz];

// ---------------- helpers ----------------------------------------------------
__device__ __forceinline__ float blockReduceSum128(float val, float* smem4) {
    int lane = threadIdx.x & 31, warp = threadIdx.x >> 5;
    #pragma unroll
    for (int o = 16; o > 0; o >>= 1) val += __shfl_down_sync(0xffffffffu, val, o);
    if (lane == 0) smem4[warp] = val;
    __syncthreads();
    float v = (threadIdx.x < 4) ? smem4[threadIdx.x] : 0.f;
    if (warp == 0) {
        v += __shfl_down_sync(0xffffffffu, v, 2);
        v += __shfl_down_sync(0xffffffffu, v, 1);
        if (lane == 0) smem4[0] = v;
    }
    __syncthreads();
    float r = smem4[0];
    __syncthreads();
    return r;
}

__device__ __forceinline__ void cpasync16(void* dst, const void* src) {
    unsigned sa = (unsigned)__cvta_generic_to_shared(dst);
    asm volatile("cp.async.cg.shared.global [%0], [%1], 16;\n" :: "r"(sa), "l"(src));
}
__device__ __forceinline__ void cp_commit() { asm volatile("cp.async.commit_group;\n"); }
__device__ __forceinline__ void cp_wait0()  { asm volatile("cp.async.wait_group 0;\n"); }

// ---------------- state init -------------------------------------------------
__global__ void init_state_kernel() {
    int t = threadIdx.x;
    if (t < Bsz) { g_active[t] = 1; g_scores[t] = 0.f; g_exitl[t] = 0; }
}

// ---------------- embeddings + LN --------------------------------------------
__global__ void embed_ln_kernel(const int* __restrict__ ids, const int* __restrict__ tts,
                                const float* __restrict__ we, const float* __restrict__ pe,
                                const float* __restrict__ te, const float* __restrict__ g,
                                const float* __restrict__ b) {
    __shared__ float red[4];
    int row = blockIdx.x, s = row & (Ssz - 1), tid = threadIdx.x;
    int id = ids[row], tt = tts[row];
    float x[3];
    #pragma unroll
    for (int i = 0; i < 3; i++) {
        int j = tid + i * 128;
        x[i] = we[id * Hsz + j] + pe[s * Hsz + j] + te[tt * Hsz + j];
    }
    float mean = blockReduceSum128(x[0] + x[1] + x[2], red) * (1.f / Hsz);
    float sq = 0.f;
    #pragma unroll
    for (int i = 0; i < 3; i++) { float d = x[i] - mean; sq += d * d; }
    float var = blockReduceSum128(sq, red) * (1.f / Hsz);
    float inv = rsqrtf(var + 1e-12f);
    #pragma unroll
    for (int i = 0; i < 3; i++) {
        int j = tid + i * 128;
        g_h[row * Hsz + j] = g[j] * (x[i] - mean) * inv + b[j];
    }
}

// ---------------- TF32 tensor-core GEMM body (cp.async double-buffered) ------
// C[MxN] = A[MxK] @ W[KxN] + bias, optional exact GELU.
// 128x128 block tile, BK=16, 256 threads (8 warps as 2x4), warp tile 64x32.
// A smem [m][k] stride 20 (conflict-free frag loads), B smem [k][n] stride 136.
struct TgemmSmem {
    float As[2][128][20];
    float Bs[2][16][136];
};

__device__ __forceinline__ void tgemm_body(
        const float* __restrict__ A, const float* __restrict__ W,
        const float* __restrict__ bias, float* __restrict__ C,
        int N, int K, int act, int bx, int by, TgemmSmem& sm) {
    const int t = threadIdx.x;
    const int lane = t & 31, warp = t >> 5;
    const int kk = lane & 3, r = lane >> 2;
    const int mw = (warp >> 2) * 64;
    const int nw = (warp & 3) * 32;
    const int br = by * 128, bc = bx * 128;

    const int arow = t >> 2, ac4 = (t & 3) * 4;    // A: 64 rows x 16 cols per half
    const int brow = t >> 5, bc4 = (t & 31) * 4;   // B: 8 rows x 128 cols per half
    const float* Ag0 = A + (size_t)(br + arow) * K + ac4;
    const float* Ag1 = Ag0 + (size_t)64 * K;
    const float* Wg0 = W + (size_t)brow * N + bc + bc4;
    const float* Wg1 = Wg0 + (size_t)8 * N;

    float acc[4][4][4] = {};

    const int T = K >> 4;
    // prologue: stage 0
    cpasync16(&sm.As[0][arow][ac4], Ag0);
    cpasync16(&sm.As[0][arow + 64][ac4], Ag1);
    cpasync16(&sm.Bs[0][brow][bc4], Wg0);
    cpasync16(&sm.Bs[0][brow + 8][bc4], Wg1);
    cp_commit();

    int buf = 0;
    for (int tt = 0; tt < T; tt++) {
        cp_wait0();
        __syncthreads();
        if (tt + 1 < T) {
            int k0 = (tt + 1) << 4;
            int nb = buf ^ 1;
            cpasync16(&sm.As[nb][arow][ac4], Ag0 + k0);
            cpasync16(&sm.As[nb][arow + 64][ac4], Ag1 + k0);
            cpasync16(&sm.Bs[nb][brow][bc4], Wg0 + (size_t)k0 * N);
            cpasync16(&sm.Bs[nb][brow + 8][bc4], Wg1 + (size_t)k0 * N);
            cp_commit();
        }
        #pragma unroll
        for (int ks = 0; ks < 16; ks += 8) {
            unsigned a[4][4], b[4][2];
            #pragma unroll
            for (int mt = 0; mt < 4; mt++) {
                int m = mw + mt * 16 + r;
                a[mt][0] = __float_as_uint(sm.As[buf][m][ks + kk]);
                a[mt][1] = __float_as_uint(sm.As[buf][m + 8][ks + kk]);
                a[mt][2] = __float_as_uint(sm.As[buf][m][ks + 4 + kk]);
                a[mt][3] = __float_as_uint(sm.As[buf][m + 8][ks + 4 + kk]);
            }
            #pragma unroll
            for (int nt = 0; nt < 4; nt++) {
                int n = nw + nt * 8 + r;
                b[nt][0] = __float_as_uint(sm.Bs[buf][ks + kk][n]);
                b[nt][1] = __float_as_uint(sm.Bs[buf][ks + 4 + kk][n]);
            }
            #pragma unroll
            for (int mt = 0; mt < 4; mt++)
                #pragma unroll
                for (int nt = 0; nt < 4; nt++) {
                    asm volatile(
                        "mma.sync.aligned.m16n8k8.row.col.f32.tf32.tf32.f32 "
                        "{%0,%1,%2,%3}, {%4,%5,%6,%7}, {%8,%9}, {%0,%1,%2,%3};"
                        : "+f"(acc[mt][nt][0]), "+f"(acc[mt][nt][1]),
                          "+f"(acc[mt][nt][2]), "+f"(acc[mt][nt][3])
                        : "r"(a[mt][0]), "r"(a[mt][1]), "r"(a[mt][2]), "r"(a[mt][3]),
                          "r"(b[nt][0]), "r"(b[nt][1]));
                }
        }
        __syncthreads();
        buf ^= 1;
    }

    // epilogue: bias (+ exact GELU), float2 stores
    #pragma unroll
    for (int nt = 0; nt < 4; nt++) {
        int col = bc + nw + nt * 8 + 2 * kk;
        float b0 = bias[col], b1 = bias[col + 1];
        #pragma unroll
        for (int mt = 0; mt < 4; mt++) {
            int row = br + mw + mt * 16 + r;
            float v0 = acc[mt][nt][0] + b0, v1 = acc[mt][nt][1] + b1;
            float v2 = acc[mt][nt][2] + b0, v3 = acc[mt][nt][3] + b1;
            if (act == 1) {
                v0 = 0.5f * v0 * (1.f + erff(v0 * 0.70710678118654752f));
                v1 = 0.5f * v1 * (1.f + erff(v1 * 0.70710678118654752f));
                v2 = 0.5f * v2 * (1.f + erff(v2 * 0.70710678118654752f));
                v3 = 0.5f * v3 * (1.f + erff(v3 * 0.70710678118654752f));
            }
            *reinterpret_cast<float2*>(&C[(size_t)row * N + col]) = make_float2(v0, v1);
            *reinterpret_cast<float2*>(&C[(size_t)(row + 8) * N + col]) = make_float2(v2, v3);
        }
    }
}

__global__ __launch_bounds__(256, 2) void tgemm_kernel(
        const float* __restrict__ A, const float* __restrict__ W,
        const float* __restrict__ bias, float* __restrict__ C,
        int N, int K, int act) {
    __shared__ TgemmSmem sm;
    tgemm_body(A, W, bias, C, N, K, act, blockIdx.x, blockIdx.y, sm);
}

// fused QKV: blockIdx.z selects projection
__global__ __launch_bounds__(256, 2) void tgemm_qkv_kernel(
        const float* __restrict__ A,
        const float* __restrict__ Wq, const float* __restrict__ Wk, const float* __restrict__ Wv,
        const float* __restrict__ bq, const float* __restrict__ bk, const float* __restrict__ bv,
        float* __restrict__ Cq, float* __restrict__ Ck, float* __restrict__ Cv) {
    __shared__ TgemmSmem sm;
    const float* Ws[3] = {Wq, Wk, Wv};
    const float* bs[3] = {bq, bk, bv};
    float* Cs[3] = {Cq, Ck, Cv};
    int z = blockIdx.z;
    tgemm_body(A, Ws[z], bs[z], Cs[z], Hsz, Hsz, 0, blockIdx.x, blockIdx.y, sm);
}

// ---------------- attention: one thread per query row, online softmax --------
__global__ void attn_kernel(const float* __restrict__ q, const float* __restrict__ k,
                            const float* __restrict__ v, const int* __restrict__ mask,
                            float* __restrict__ ctx) {
    __shared__ float Ks[128 * 32];
    __shared__ float Vs[128 * 32];
    __shared__ float bi[256];
    int head = blockIdx.x, b = blockIdx.y, tid = threadIdx.x;   // 256 threads
    bi[tid] = (1.f - (float)mask[b * Ssz + tid]) * -1e9f;

    float qr[32];
    const float* qp = q + (size_t)(b * Ssz + tid) * Hsz + head * DHs;
    #pragma unroll
    for (int d = 0; d < 32; d += 4) {
        float4 qq = *reinterpret_cast<const float4*>(qp + d);
        qr[d] = qq.x; qr[d + 1] = qq.y; qr[d + 2] = qq.z; qr[d + 3] = qq.w;
    }
    float m = -1e30f, l = 0.f, o[32];
    #pragma unroll
    for (int d = 0; d < 32; d++) o[d] = 0.f;

    for (int tile = 0; tile < 2; tile++) {
        int keybase = tile * 128;
        #pragma unroll
        for (int i = 0; i < 16; i++) {
            int e = tid + i * 256;
            int kj = e >> 5, kd = e & 31;
            size_t gidx = (size_t)(b * Ssz + keybase + kj) * Hsz + head * DHs + kd;
            Ks[e] = k[gidx];
            Vs[e] = v[gidx];
        }
        __syncthreads();
        for (int j = 0; j < 128; j++) {
            const float* kr = &Ks[j * 32];
            float s = 0.f;
            #pragma unroll
            for (int d = 0; d < 32; d++) s = fmaf(qr[d], kr[d], s);
            s = s * 0.17677669529663688f + bi[keybase + j];   // 1/sqrt(32)
            if (s > m) {   // rare rescale path
                float corr = __expf(m - s);
                l *= corr;
                #pragma unroll
                for (int d = 0; d < 32; d++) o[d] *= corr;
                m = s;
            }
            float p = __expf(s - m);
            l += p;
            const float* vr = &Vs[j * 32];
            #pragma unroll
            for (int d = 0; d < 32; d++) o[d] = fmaf(p, vr[d], o[d]);
        }
        __syncthreads();
    }
    float invl = 1.f / l;
    float* cp = ctx + (size_t)(b * Ssz + tid) * Hsz + head * DHs;
    #pragma unroll
    for (int d = 0; d < 32; d++) cp[d] = o[d] * invl;
}

// ---------------- residual + LN: h = LN(h + delta) ---------------------------
__global__ void residual_ln_kernel(const float* __restrict__ delta,
                                   const float* __restrict__ g, const float* __restrict__ b) {
    __shared__ float red[4];
    int row = blockIdx.x, tid = threadIdx.x;
    float x[3];
    #pragma unroll
    for (int i = 0; i < 3; i++) {
        int j = tid + i * 128;
        x[i] = g_h[(size_t)row * Hsz + j] + delta[(size_t)row * Hsz + j];
    }
    float mean = blockReduceSum128(x[0] + x[1] + x[2], red) * (1.f / Hsz);
    float sq = 0.f;
    #pragma unroll
    for (int i = 0; i < 3; i++) { float d = x[i] - mean; sq += d * d; }
    float var = blockReduceSum128(sq, red) * (1.f / Hsz);
    float inv = rsqrtf(var + 1e-12f);
    #pragma unroll
    for (int i = 0; i < 3; i++) {
        int j = tid + i * 128;
        g_h[(size_t)row * Hsz + j] = g[j] * (x[i] - mean) * inv + b[j];
    }
}

// ---------------- offramp: entropy decision on CLS token ---------------------
__global__ void offramp_kernel(const float* __restrict__ Wr, const float* __restrict__ br,
                               int layer) {
    __shared__ float w[Hsz];
    int tid = threadIdx.x;  // 128
    #pragma unroll
    for (int i = 0; i < 3; i++) w[tid + i * 128] = Wr[layer * Hsz + tid + i * 128];
    __syncthreads();
    int b = tid;
    const float* hr = g_h + (size_t)(b * Ssz) * Hsz;
    float l = br[layer];
    for (int kk = 0; kk < Hsz; kk++) l = fmaf(hr[kk], w[kk], l);
    float lsp = (l > 0.f) ? -log1pf(expf(-l)) : (l - log1pf(expf(l)));
    float lsn = (l < 0.f) ? -log1pf(expf(l)) : (-l - log1pf(expf(-l)));
    float p = 1.f / (1.f + expf(-l));
    float ent = -(p * lsp + (1.f - p) * lsn);
    if (g_active[b] && ent < 0.1f) {
        g_scores[b] = l; g_exitl[b] = layer; g_active[b] = 0;
    }
}

// ---------------- pooler -----------------------------------------------------
__global__ void pooler_kernel(const float* __restrict__ Wp, const float* __restrict__ bp) {
    __shared__ float hr[Hsz];
    int b = blockIdx.x, tid = threadIdx.x;   // 384 threads
    hr[tid] = g_h[(size_t)(b * Ssz) * Hsz + tid];
    __syncthreads();
    float acc = bp[tid];
    for (int kk = 0; kk < Hsz; kk++) acc = fmaf(hr[kk], Wp[kk * Hsz + tid], acc);
    g_pooled[b * Hsz + tid] = tanhf(acc);
}

// ---------------- final classifier + output assembly -------------------------
__global__ void final_kernel(const float* __restrict__ Wc, const float* __restrict__ bc,
                             float* __restrict__ out, int out_size) {
    __shared__ int counts[8];
    int tid = threadIdx.x;  // 128
    if (tid < 8) counts[tid] = 0;
    __syncthreads();
    int b = tid;
    float acc = bc[0];
    for (int kk = 0; kk < Hsz; kk++) acc = fmaf(g_pooled[b * Hsz + kk], Wc[kk], acc);
    float sc; int el;
    if (g_active[b]) { sc = acc; el = NOFF; }
    else             { sc = g_scores[b]; el = g_exitl[b]; }
    atomicAdd(&counts[el], 1);
    __syncthreads();
    out[b] = sc;
    out[Bsz + b] = (float)el;
    if (tid < NOFF + 1) out[2 * Bsz + tid] = (float)counts[tid];
    for (int i = 2 * Bsz + NOFF + 1 + tid; i < out_size; i += 128) out[i] = 0.f;
}

// ---------------- launch -----------------------------------------------------
extern "C" void kernel_launch(void* const* d_in, const int* in_sizes, int n_in,
                              void* d_out, int out_size) {
    (void)in_sizes; (void)n_in;
    const int*   input_ids      = (const int*)d_in[0];
    const int*   attention_mask = (const int*)d_in[1];
    const int*   token_type_ids = (const int*)d_in[2];
    const float* word_emb = (const float*)d_in[3];
    const float* pos_emb  = (const float*)d_in[4];
    const float* type_emb = (const float*)d_in[5];
    const float* emb_ln_g = (const float*)d_in[6];
    const float* emb_ln_b = (const float*)d_in[7];
    const float* Wq = (const float*)d_in[8];  const float* bq = (const float*)d_in[9];
    const float* Wk = (const float*)d_in[10]; const float* bk = (const float*)d_in[11];
    const float* Wv = (const float*)d_in[12]; const float* bv = (const float*)d_in[13];
    const float* Wo = (const float*)d_in[14]; const float* bo = (const float*)d_in[15];
    const float* ln1_g = (const float*)d_in[16]; const float* ln1_b = (const float*)d_in[17];
    const float* Wi = (const float*)d_in[18]; const float* bi = (const float*)d_in[19];
    const float* Wfo = (const float*)d_in[20]; const float* bfo = (const float*)d_in[21];
    const float* ln2_g = (const float*)d_in[22]; const float* ln2_b = (const float*)d_in[23];
    const float* Wp = (const float*)d_in[24]; const float* bp = (const float*)d_in[25];
    const float* Wc = (const float*)d_in[26]; const float* bc = (const float*)d_in[27];
    const float* Wr = (const float*)d_in[28]; const float* br = (const float*)d_in[29];

    float *hp, *qp, *kp, *vp, *cp, *tp, *fp;
    cudaGetSymbolAddress((void**)&hp, g_h);
    cudaGetSymbolAddress((void**)&qp, g_q);
    cudaGetSymbolAddress((void**)&kp, g_k);
    cudaGetSymbolAddress((void**)&vp, g_v);
    cudaGetSymbolAddress((void**)&cp, g_ctx);
    cudaGetSymbolAddress((void**)&tp, g_tmp);
    cudaGetSymbolAddress((void**)&fp, g_ff);

    init_state_kernel<<<1, 128>>>();
    embed_ln_kernel<<<ROWS, 128>>>(input_ids, token_type_ids, word_emb, pos_emb, type_emb,
                                   emb_ln_g, emb_ln_b);

    dim3 gHH(Hsz / 128, ROWS / 128);          // (3, 256)
    dim3 gQKV(Hsz / 128, ROWS / 128, 3);      // (3, 256, 3)
    dim3 gHF(Fsz / 128, ROWS / 128);          // (12, 256)

    for (int i = 0; i < Lyr; i++) {
        const float* wq = Wq + (size_t)i * Hsz * Hsz;
        const float* wk = Wk + (size_t)i * Hsz * Hsz;
        const float* wv = Wv + (size_t)i * Hsz * Hsz;
        const float* wo = Wo + (size_t)i * Hsz * Hsz;
        tgemm_qkv_kernel<<<gQKV, 256>>>(hp, wq, wk, wv,
                                        bq + i * Hsz, bk + i * Hsz, bv + i * Hsz,
                                        qp, kp, vp);
        attn_kernel<<<dim3(NHs, Bsz), 256>>>(qp, kp, vp, attention_mask, cp);
        tgemm_kernel<<<gHH, 256>>>(cp, wo, bo + i * Hsz, tp, Hsz, Hsz, 0);
        residual_ln_kernel<<<ROWS, 128>>>(tp, ln1_g + i * Hsz, ln1_b + i * Hsz);
        tgemm_kernel<<<gHF, 256>>>(hp, Wi + (size_t)i * Hsz * Fsz, bi + i * Fsz, fp,
                                   Fsz, Hsz, 1);
        tgemm_kernel<<<gHH, 256>>>(fp, Wfo + (size_t)i * Fsz * Hsz, bfo + i * Hsz, tp,
                                   Hsz, Fsz, 0);
        residual_ln_kernel<<<ROWS, 128>>>(tp, ln2_g + i * Hsz, ln2_b + i * Hsz);
        if (i < NOFF) {
            offramp_kernel<<<1, 128>>>(Wr, br, i);
            // maskrows removed: exited docs' hidden states are observationally dead
            // (offramp gated on g_active; docs independent; scores come from g_scores)
        }
    }
    pooler_kernel<<<Bsz, Hsz>>>(Wp, bp);
    final_kernel<<<1, 128>>>(Wc, bc, (float*)d_out, out_size);
}

// round 5
// speedup vs baseline: 3.5843x; 1.3723x over previous
#include <cuda_runtime.h>
#include <math.h>

#define Bsz 128
#define Ssz 256
#define Hsz 384
#define NHs 12
#define DHs 32
#define Fsz 1536
#define Lyr 6
#define NOFF 5
#define ROWS (Bsz*Ssz)   /* 32768 */

// ---------------- scratch (static device globals; no allocation) --------------
__device__ float g_h[ROWS*Hsz];
__device__ float g_q[ROWS*Hsz];
__device__ float g_k[ROWS*Hsz];
__device__ float g_v[ROWS*Hsz];
__device__ float g_ctx[ROWS*Hsz];
__device__ float g_tmp[ROWS*Hsz];
__device__ float g_ff[ROWS*Fsz];
__device__ float g_pooled[Bsz*Hsz];
__device__ int   g_active[Bsz];
__device__ float g_scores[Bsz];
__device__ int   g_exitl[Bsz];

// ---------------- helpers ----------------------------------------------------
__device__ __forceinline__ float blockReduceSum128(float val, float* smem4) {
    int lane = threadIdx.x & 31, warp = threadIdx.x >> 5;
    #pragma unroll
    for (int o = 16; o > 0; o >>= 1) val += __shfl_down_sync(0xffffffffu, val, o);
    if (lane == 0) smem4[warp] = val;
    __syncthreads();
    float v = (threadIdx.x < 4) ? smem4[threadIdx.x] : 0.f;
    if (warp == 0) {
        v += __shfl_down_sync(0xffffffffu, v, 2);
        v += __shfl_down_sync(0xffffffffu, v, 1);
        if (lane == 0) smem4[0] = v;
    }
    __syncthreads();
    float r = smem4[0];
    __syncthreads();
    return r;
}

__device__ __forceinline__ void cpasync16(void* dst, const void* src) {
    unsigned sa = (unsigned)__cvta_generic_to_shared(dst);
    asm volatile("cp.async.cg.shared.global [%0], [%1], 16;\n" :: "r"(sa), "l"(src));
}
__device__ __forceinline__ void cp_commit() { asm volatile("cp.async.commit_group;\n"); }
__device__ __forceinline__ void cp_wait0()  { asm volatile("cp.async.wait_group 0;\n"); }

__device__ __forceinline__ float tf32r(float x) {   // round-to-nearest tf32, as float bits
    unsigned u;
    asm("cvt.rna.tf32.f32 %0, %1;" : "=r"(u) : "f"(x));
    return __uint_as_float(u);
}

#define MMA_TF32(d, a, bfr) \
    asm volatile("mma.sync.aligned.m16n8k8.row.col.f32.tf32.tf32.f32 " \
        "{%0,%1,%2,%3}, {%4,%5,%6,%7}, {%8,%9}, {%0,%1,%2,%3};" \
        : "+f"((d)[0]), "+f"((d)[1]), "+f"((d)[2]), "+f"((d)[3]) \
        : "r"((a)[0]), "r"((a)[1]), "r"((a)[2]), "r"((a)[3]), \
          "r"((bfr)[0]), "r"((bfr)[1]))

// ---------------- state init -------------------------------------------------
__global__ void init_state_kernel() {
    int t = threadIdx.x;
    if (t < Bsz) { g_active[t] = 1; g_scores[t] = 0.f; g_exitl[t] = 0; }
}

// ---------------- embeddings + LN --------------------------------------------
__global__ void embed_ln_kernel(const int* __restrict__ ids, const int* __restrict__ tts,
                                const float* __restrict__ we, const float* __restrict__ pe,
                                const float* __restrict__ te, const float* __restrict__ g,
                                const float* __restrict__ b) {
    __shared__ float red[4];
    int row = blockIdx.x, s = row & (Ssz - 1), tid = threadIdx.x;
    int id = ids[row], tt = tts[row];
    float x[3];
    #pragma unroll
    for (int i = 0; i < 3; i++) {
        int j = tid + i * 128;
        x[i] = we[id * Hsz + j] + pe[s * Hsz + j] + te[tt * Hsz + j];
    }
    float mean = blockReduceSum128(x[0] + x[1] + x[2], red) * (1.f / Hsz);
    float sq = 0.f;
    #pragma unroll
    for (int i = 0; i < 3; i++) { float d = x[i] - mean; sq += d * d; }
    float var = blockReduceSum128(sq, red) * (1.f / Hsz);
    float inv = rsqrtf(var + 1e-12f);
    #pragma unroll
    for (int i = 0; i < 3; i++) {
        int j = tid + i * 128;
        g_h[row * Hsz + j] = g[j] * (x[i] - mean) * inv + b[j];
    }
}

// ---------------- TF32 tensor-core GEMM body (cp.async double-buffered) ------
struct TgemmSmem {
    float As[2][128][20];
    float Bs[2][16][136];
};

__device__ __forceinline__ void tgemm_body(
        const float* __restrict__ A, const float* __restrict__ W,
        const float* __restrict__ bias, float* __restrict__ C,
        int N, int K, int act, int bx, int by, TgemmSmem& sm) {
    const int t = threadIdx.x;
    const int lane = t & 31, warp = t >> 5;
    const int kk = lane & 3, r = lane >> 2;
    const int mw = (warp >> 2) * 64;
    const int nw = (warp & 3) * 32;
    const int br = by * 128, bc = bx * 128;

    const int arow = t >> 2, ac4 = (t & 3) * 4;
    const int brow = t >> 5, bc4 = (t & 31) * 4;
    const float* Ag0 = A + (size_t)(br + arow) * K + ac4;
    const float* Ag1 = Ag0 + (size_t)64 * K;
    const float* Wg0 = W + (size_t)brow * N + bc + bc4;
    const float* Wg1 = Wg0 + (size_t)8 * N;

    float acc[4][4][4] = {};

    const int T = K >> 4;
    cpasync16(&sm.As[0][arow][ac4], Ag0);
    cpasync16(&sm.As[0][arow + 64][ac4], Ag1);
    cpasync16(&sm.Bs[0][brow][bc4], Wg0);
    cpasync16(&sm.Bs[0][brow + 8][bc4], Wg1);
    cp_commit();

    int buf = 0;
    for (int tt = 0; tt < T; tt++) {
        cp_wait0();
        __syncthreads();
        if (tt + 1 < T) {
            int k0 = (tt + 1) << 4;
            int nb = buf ^ 1;
            cpasync16(&sm.As[nb][arow][ac4], Ag0 + k0);
            cpasync16(&sm.As[nb][arow + 64][ac4], Ag1 + k0);
            cpasync16(&sm.Bs[nb][brow][bc4], Wg0 + (size_t)k0 * N);
            cpasync16(&sm.Bs[nb][brow + 8][bc4], Wg1 + (size_t)k0 * N);
            cp_commit();
        }
        #pragma unroll
        for (int ks = 0; ks < 16; ks += 8) {
            unsigned a[4][4], b[4][2];
            #pragma unroll
            for (int mt = 0; mt < 4; mt++) {
                int m = mw + mt * 16 + r;
                a[mt][0] = __float_as_uint(sm.As[buf][m][ks + kk]);
                a[mt][1] = __float_as_uint(sm.As[buf][m + 8][ks + kk]);
                a[mt][2] = __float_as_uint(sm.As[buf][m][ks + 4 + kk]);
                a[mt][3] = __float_as_uint(sm.As[buf][m + 8][ks + 4 + kk]);
            }
            #pragma unroll
            for (int nt = 0; nt < 4; nt++) {
                int n = nw + nt * 8 + r;
                b[nt][0] = __float_as_uint(sm.Bs[buf][ks + kk][n]);
                b[nt][1] = __float_as_uint(sm.Bs[buf][ks + 4 + kk][n]);
            }
            #pragma unroll
            for (int mt = 0; mt < 4; mt++)
                #pragma unroll
                for (int nt = 0; nt < 4; nt++)
                    MMA_TF32(acc[mt][nt], a[mt], b[nt]);
        }
        __syncthreads();
        buf ^= 1;
    }

    #pragma unroll
    for (int nt = 0; nt < 4; nt++) {
        int col = bc + nw + nt * 8 + 2 * kk;
        float b0 = bias[col], b1 = bias[col + 1];
        #pragma unroll
        for (int mt = 0; mt < 4; mt++) {
            int row = br + mw + mt * 16 + r;
            float v0 = acc[mt][nt][0] + b0, v1 = acc[mt][nt][1] + b1;
            float v2 = acc[mt][nt][2] + b0, v3 = acc[mt][nt][3] + b1;
            if (act == 1) {
                v0 = 0.5f * v0 * (1.f + erff(v0 * 0.70710678118654752f));
                v1 = 0.5f * v1 * (1.f + erff(v1 * 0.70710678118654752f));
                v2 = 0.5f * v2 * (1.f + erff(v2 * 0.70710678118654752f));
                v3 = 0.5f * v3 * (1.f + erff(v3 * 0.70710678118654752f));
            }
            *reinterpret_cast<float2*>(&C[(size_t)row * N + col]) = make_float2(v0, v1);
            *reinterpret_cast<float2*>(&C[(size_t)(row + 8) * N + col]) = make_float2(v2, v3);
        }
    }
}

__global__ __launch_bounds__(256, 2) void tgemm_kernel(
        const float* __restrict__ A, const float* __restrict__ W,
        const float* __restrict__ bias, float* __restrict__ C,
        int N, int K, int act) {
    __shared__ TgemmSmem sm;
    tgemm_body(A, W, bias, C, N, K, act, blockIdx.x, blockIdx.y, sm);
}

__global__ __launch_bounds__(256, 2) void tgemm_qkv_kernel(
        const float* __restrict__ A,
        const float* __restrict__ Wq, const float* __restrict__ Wk, const float* __restrict__ Wv,
        const float* __restrict__ bq, const float* __restrict__ bk, const float* __restrict__ bv,
        float* __restrict__ Cq, float* __restrict__ Ck, float* __restrict__ Cv) {
    __shared__ TgemmSmem sm;
    const float* Ws[3] = {Wq, Wk, Wv};
    const float* bs[3] = {bq, bk, bv};
    float* Cs[3] = {Cq, Ck, Cv};
    int z = blockIdx.z;
    tgemm_body(A, Ws[z], bs[z], Cs[z], Hsz, Hsz, 0, blockIdx.x, blockIdx.y, sm);
}

// ---------------- tensor-core flash attention --------------------------------
// One block per (batch, head). 8 warps x 32 query rows. Key tiles of 32.
// Smem: Ks[256][36] (stride 36 => conflict-free B-frags), Vt[32][260] (V^T),
// Pw[8][32][36] per-warp P relayout buffer, bias[256].
#define ATTN_SMEM_FLOATS (256*36 + 32*260 + 8*32*36 + 256)
#define ATTN_SMEM_BYTES  (ATTN_SMEM_FLOATS * 4)
#define SCL 0.17677669529663688f

__global__ __launch_bounds__(256, 2) void attn_mma_kernel(
        const float* __restrict__ q, const float* __restrict__ k,
        const float* __restrict__ v, const int* __restrict__ mask,
        float* __restrict__ ctx) {
    extern __shared__ float sm[];
    float* Ks = sm;                     // [256][36]
    float* Vt = sm + 256*36;            // [32][260]
    float* Pw = Vt + 32*260;            // [8][32][36]
    float* bi = Pw + 8*32*36;           // [256]

    const int h = blockIdx.x, b = blockIdx.y;
    const int tid = threadIdx.x, lane = tid & 31, w = tid >> 5;
    const int gr = lane >> 2, kk = lane & 3;

    for (int idx = tid; idx < 256*32; idx += 256) {
        int key = idx >> 5, d = idx & 31;
        size_t gi = (size_t)(b*Ssz + key)*Hsz + h*DHs + d;
        Ks[key*36 + d] = tf32r(k[gi]);
        Vt[d*260 + key] = tf32r(v[gi]);
    }
    bi[tid] = (1.f - (float)mask[b*Ssz + tid]) * -1e9f;
    __syncthreads();

    // Q fragments: rows w*32 .. w*32+31, all 32 dims (4 k-steps)
    unsigned aq[2][4][4];
    const int qrow0 = b*Ssz + w*32 + gr;
    #pragma unroll
    for (int mt = 0; mt < 2; mt++)
        #pragma unroll
        for (int kt = 0; kt < 4; kt++) {
            const float* qp = q + (size_t)(qrow0 + mt*16)*Hsz + h*DHs + kt*8 + kk;
            aq[mt][kt][0] = __float_as_uint(tf32r(qp[0]));
            aq[mt][kt][1] = __float_as_uint(tf32r(qp[8*(size_t)Hsz]));
            aq[mt][kt][2] = __float_as_uint(tf32r(qp[4]));
            aq[mt][kt][3] = __float_as_uint(tf32r(qp[8*(size_t)Hsz + 4]));
        }

    float m_[2][2] = {{-1e30f, -1e30f}, {-1e30f, -1e30f}};
    float l_[2][2] = {};
    float o[2][4][4] = {};
    float* pw = Pw + w*(32*36);

    for (int t = 0; t < 8; t++) {
        const int kb = t*32;
        // S = Q @ K^T for 32 q-rows x 32 keys
        float s[2][4][4] = {};
        #pragma unroll
        for (int kt = 0; kt < 4; kt++) {
            unsigned bf[4][2];
            #pragma unroll
            for (int nt = 0; nt < 4; nt++) {
                const float* kp = &Ks[(kb + nt*8 + gr)*36 + kt*8 + kk];
                bf[nt][0] = __float_as_uint(kp[0]);
                bf[nt][1] = __float_as_uint(kp[4]);
            }
            #pragma unroll
            for (int mt = 0; mt < 2; mt++)
                #pragma unroll
                for (int nt = 0; nt < 4; nt++)
                    MMA_TF32(s[mt][nt], aq[mt][kt], bf[nt]);
        }
        // scale + mask bias
        #pragma unroll
        for (int nt = 0; nt < 4; nt++) {
            float2 bv = *reinterpret_cast<const float2*>(&bi[kb + nt*8 + 2*kk]);
            #pragma unroll
            for (int mt = 0; mt < 2; mt++) {
                s[mt][nt][0] = s[mt][nt][0]*SCL + bv.x;
                s[mt][nt][1] = s[mt][nt][1]*SCL + bv.y;
                s[mt][nt][2] = s[mt][nt][2]*SCL + bv.x;
                s[mt][nt][3] = s[mt][nt][3]*SCL + bv.y;
            }
        }
        // online softmax: row stats per (mt, half); quad reduce over kk lanes
        #pragma unroll
        for (int mt = 0; mt < 2; mt++) {
            #pragma unroll
            for (int hf = 0; hf < 2; hf++) {
                float tm = -1e30f;
                #pragma unroll
                for (int nt = 0; nt < 4; nt++)
                    tm = fmaxf(tm, fmaxf(s[mt][nt][2*hf], s[mt][nt][2*hf+1]));
                tm = fmaxf(tm, __shfl_xor_sync(0xffffffffu, tm, 1));
                tm = fmaxf(tm, __shfl_xor_sync(0xffffffffu, tm, 2));
                float nm = fmaxf(m_[mt][hf], tm);
                float corr = __expf(m_[mt][hf] - nm);
                m_[mt][hf] = nm;
                float rs = 0.f;
                #pragma unroll
                for (int nt = 0; nt < 4; nt++) {
                    float p0 = __expf(s[mt][nt][2*hf] - nm);
                    float p1 = __expf(s[mt][nt][2*hf+1] - nm);
                    s[mt][nt][2*hf] = p0; s[mt][nt][2*hf+1] = p1;
                    rs += p0 + p1;
                    o[mt][nt][2*hf]   *= corr;
                    o[mt][nt][2*hf+1] *= corr;
                }
                rs += __shfl_xor_sync(0xffffffffu, rs, 1);
                rs += __shfl_xor_sync(0xffffffffu, rs, 2);
                l_[mt][hf] = l_[mt][hf]*corr + rs;
            }
        }
        // relayout P through per-warp smem (C-frag -> A-frag)
        #pragma unroll
        for (int mt = 0; mt < 2; mt++)
            #pragma unroll
            for (int nt = 0; nt < 4; nt++) {
                *reinterpret_cast<float2*>(&pw[(mt*16+gr)*36 + nt*8 + 2*kk]) =
                    make_float2(s[mt][nt][0], s[mt][nt][1]);
                *reinterpret_cast<float2*>(&pw[(mt*16+gr+8)*36 + nt*8 + 2*kk]) =
                    make_float2(s[mt][nt][2], s[mt][nt][3]);
            }
        __syncwarp();
        // O += P @ V   (B-frags from transposed V)
        #pragma unroll
        for (int kt = 0; kt < 4; kt++) {
            unsigned ap[2][4];
            #pragma unroll
            for (int mt = 0; mt < 2; mt++) {
                ap[mt][0] = __float_as_uint(pw[(mt*16+gr)*36 + kt*8 + kk]);
                ap[mt][1] = __float_as_uint(pw[(mt*16+gr+8)*36 + kt*8 + kk]);
                ap[mt][2] = __float_as_uint(pw[(mt*16+gr)*36 + kt*8 + kk + 4]);
                ap[mt][3] = __float_as_uint(pw[(mt*16+gr+8)*36 + kt*8 + kk + 4]);
            }
            unsigned bf[4][2];
            #pragma unroll
            for (int nt = 0; nt < 4; nt++) {
                const float* vp = &Vt[(nt*8+gr)*260 + kb + kt*8 + kk];
                bf[nt][0] = __float_as_uint(vp[0]);
                bf[nt][1] = __float_as_uint(vp[4]);
            }
            #pragma unroll
            for (int mt = 0; mt < 2; mt++)
                #pragma unroll
                for (int nt = 0; nt < 4; nt++)
                    MMA_TF32(o[mt][nt], ap[mt], bf[nt]);
        }
        __syncwarp();
    }

    // normalize + write ctx
    #pragma unroll
    for (int mt = 0; mt < 2; mt++) {
        float i0 = 1.f / l_[mt][0], i1 = 1.f / l_[mt][1];
        #pragma unroll
        for (int nt = 0; nt < 4; nt++) {
            size_t base = (size_t)(qrow0 + mt*16)*Hsz + h*DHs + nt*8 + 2*kk;
            *reinterpret_cast<float2*>(&ctx[base]) =
                make_float2(o[mt][nt][0]*i0, o[mt][nt][1]*i0);
            *reinterpret_cast<float2*>(&ctx[base + 8*(size_t)Hsz]) =
                make_float2(o[mt][nt][2]*i1, o[mt][nt][3]*i1);
        }
    }
}

// ---------------- residual + LN: h = LN(h + delta) ---------------------------
__global__ void residual_ln_kernel(const float* __restrict__ delta,
                                   const float* __restrict__ g, const float* __restrict__ b) {
    __shared__ float red[4];
    int row = blockIdx.x, tid = threadIdx.x;
    float x[3];
    #pragma unroll
    for (int i = 0; i < 3; i++) {
        int j = tid + i * 128;
        x[i] = g_h[(size_t)row * Hsz + j] + delta[(size_t)row * Hsz + j];
    }
    float mean = blockReduceSum128(x[0] + x[1] + x[2], red) * (1.f / Hsz);
    float sq = 0.f;
    #pragma unroll
    for (int i = 0; i < 3; i++) { float d = x[i] - mean; sq += d * d; }
    float var = blockReduceSum128(sq, red) * (1.f / Hsz);
    float inv = rsqrtf(var + 1e-12f);
    #pragma unroll
    for (int i = 0; i < 3; i++) {
        int j = tid + i * 128;
        g_h[(size_t)row * Hsz + j] = g[j] * (x[i] - mean) * inv + b[j];
    }
}

// ---------------- offramp: entropy decision on CLS token ---------------------
__global__ void offramp_kernel(const float* __restrict__ Wr, const float* __restrict__ br,
                               int layer) {
    __shared__ float w[Hsz];
    int tid = threadIdx.x;  // 128
    #pragma unroll
    for (int i = 0; i < 3; i++) w[tid + i * 128] = Wr[layer * Hsz + tid + i * 128];
    __syncthreads();
    int b = tid;
    const float* hr = g_h + (size_t)(b * Ssz) * Hsz;
    float l = br[layer];
    for (int kk = 0; kk < Hsz; kk++) l = fmaf(hr[kk], w[kk], l);
    float lsp = (l > 0.f) ? -log1pf(expf(-l)) : (l - log1pf(expf(l)));
    float lsn = (l < 0.f) ? -log1pf(expf(l)) : (-l - log1pf(expf(-l)));
    float p = 1.f / (1.f + expf(-l));
    float ent = -(p * lsp + (1.f - p) * lsn);
    if (g_active[b] && ent < 0.1f) {
        g_scores[b] = l; g_exitl[b] = layer; g_active[b] = 0;
    }
}

// ---------------- pooler -----------------------------------------------------
__global__ void pooler_kernel(const float* __restrict__ Wp, const float* __restrict__ bp) {
    __shared__ float hr[Hsz];
    int b = blockIdx.x, tid = threadIdx.x;   // 384 threads
    hr[tid] = g_h[(size_t)(b * Ssz) * Hsz + tid];
    __syncthreads();
    float acc = bp[tid];
    for (int kk = 0; kk < Hsz; kk++) acc = fmaf(hr[kk], Wp[kk * Hsz + tid], acc);
    g_pooled[b * Hsz + tid] = tanhf(acc);
}

// ---------------- final classifier + output assembly -------------------------
__global__ void final_kernel(const float* __restrict__ Wc, const float* __restrict__ bc,
                             float* __restrict__ out, int out_size) {
    __shared__ int counts[8];
    int tid = threadIdx.x;  // 128
    if (tid < 8) counts[tid] = 0;
    __syncthreads();
    int b = tid;
    float acc = bc[0];
    for (int kk = 0; kk < Hsz; kk++) acc = fmaf(g_pooled[b * Hsz + kk], Wc[kk], acc);
    float sc; int el;
    if (g_active[b]) { sc = acc; el = NOFF; }
    else             { sc = g_scores[b]; el = g_exitl[b]; }
    atomicAdd(&counts[el], 1);
    __syncthreads();
    out[b] = sc;
    out[Bsz + b] = (float)el;
    if (tid < NOFF + 1) out[2 * Bsz + tid] = (float)counts[tid];
    for (int i = 2 * Bsz + NOFF + 1 + tid; i < out_size; i += 128) out[i] = 0.f;
}

// ---------------- launch -----------------------------------------------------
extern "C" void kernel_launch(void* const* d_in, const int* in_sizes, int n_in,
                              void* d_out, int out_size) {
    (void)in_sizes; (void)n_in;
    const int*   input_ids      = (const int*)d_in[0];
    const int*   attention_mask = (const int*)d_in[1];
    const int*   token_type_ids = (const int*)d_in[2];
    const float* word_emb = (const float*)d_in[3];
    const float* pos_emb  = (const float*)d_in[4];
    const float* type_emb = (const float*)d_in[5];
    const float* emb_ln_g = (const float*)d_in[6];
    const float* emb_ln_b = (const float*)d_in[7];
    const float* Wq = (const float*)d_in[8];  const float* bq = (const float*)d_in[9];
    const float* Wk = (const float*)d_in[10]; const float* bk = (const float*)d_in[11];
    const float* Wv = (const float*)d_in[12]; const float* bv = (const float*)d_in[13];
    const float* Wo = (const float*)d_in[14]; const float* bo = (const float*)d_in[15];
    const float* ln1_g = (const float*)d_in[16]; const float* ln1_b = (const float*)d_in[17];
    const float* Wi = (const float*)d_in[18]; const float* bi = (const float*)d_in[19];
    const float* Wfo = (const float*)d_in[20]; const float* bfo = (const float*)d_in[21];
    const float* ln2_g = (const float*)d_in[22]; const float* ln2_b = (const float*)d_in[23];
    const float* Wp = (const float*)d_in[24]; const float* bp = (const float*)d_in[25];
    const float* Wc = (const float*)d_in[26]; const float* bc = (const float*)d_in[27];
    const float* Wr = (const float*)d_in[28]; const float* br = (const float*)d_in[29];

    float *hp, *qp, *kp, *vp, *cp, *tp, *fp;
    cudaGetSymbolAddress((void**)&hp, g_h);
    cudaGetSymbolAddress((void**)&qp, g_q);
    cudaGetSymbolAddress((void**)&kp, g_k);
    cudaGetSymbolAddress((void**)&vp, g_v);
    cudaGetSymbolAddress((void**)&cp, g_ctx);
    cudaGetSymbolAddress((void**)&tp, g_tmp);
    cudaGetSymbolAddress((void**)&fp, g_ff);

    cudaFuncSetAttribute(attn_mma_kernel,
                         cudaFuncAttributeMaxDynamicSharedMemorySize, ATTN_SMEM_BYTES);

    init_state_kernel<<<1, 128>>>();
    embed_ln_kernel<<<ROWS, 128>>>(input_ids, token_type_ids, word_emb, pos_emb, type_emb,
                                   emb_ln_g, emb_ln_b);

    dim3 gHH(Hsz / 128, ROWS / 128);          // (3, 256)
    dim3 gQKV(Hsz / 128, ROWS / 128, 3);      // (3, 256, 3)
    dim3 gHF(Fsz / 128, ROWS / 128);          // (12, 256)

    for (int i = 0; i < Lyr; i++) {
        const float* wq = Wq + (size_t)i * Hsz * Hsz;
        const float* wk = Wk + (size_t)i * Hsz * Hsz;
        const float* wv = Wv + (size_t)i * Hsz * Hsz;
        const float* wo = Wo + (size_t)i * Hsz * Hsz;
        tgemm_qkv_kernel<<<gQKV, 256>>>(hp, wq, wk, wv,
                                        bq + i * Hsz, bk + i * Hsz, bv + i * Hsz,
                                        qp, kp, vp);
        attn_mma_kernel<<<dim3(NHs, Bsz), 256, ATTN_SMEM_BYTES>>>(qp, kp, vp,
                                                                  attention_mask, cp);
        tgemm_kernel<<<gHH, 256>>>(cp, wo, bo + i * Hsz, tp, Hsz, Hsz, 0);
        residual_ln_kernel<<<ROWS, 128>>>(tp, ln1_g + i * Hsz, ln1_b + i * Hsz);
        tgemm_kernel<<<gHF, 256>>>(hp, Wi + (size_t)i * Hsz * Fsz, bi + i * Fsz, fp,
                                   Fsz, Hsz, 1);
        tgemm_kernel<<<gHH, 256>>>(fp, Wfo + (size_t)i * Fsz * Hsz, bfo + i * Hsz, tp,
                                   Hsz, Fsz, 0);
        residual_ln_kernel<<<ROWS, 128>>>(tp, ln2_g + i * Hsz, ln2_b + i * Hsz);
        if (i < NOFF) {
            offramp_kernel<<<1, 128>>>(Wr, br, i);
        }
    }
    pooler_kernel<<<Bsz, Hsz>>>(Wp, bp);
    final_kernel<<<1, 128>>>(Wc, bc, (float*)d_out, out_size);
}

// round 8
// speedup vs baseline: 3.7539x; 1.0473x over previous
#include <cuda_runtime.h>
#include <math.h>

#define Bsz 128
#define Ssz 256
#define Hsz 384
#define NHs 12
#define DHs 32
#define Fsz 1536
#define Lyr 6
#define NOFF 5
#define ROWS (Bsz*Ssz)   /* 32768 */

// ---------------- scratch (static device globals; no allocation) --------------
__device__ float g_h[ROWS*Hsz];
__device__ float g_q[ROWS*Hsz];
__device__ float g_k[ROWS*Hsz];
__device__ float g_v[ROWS*Hsz];
__device__ float g_ctx[ROWS*Hsz];
__device__ float g_tmp[ROWS*Hsz];
__device__ float g_ff[ROWS*Fsz];
__device__ float g_pooled[Bsz*Hsz];
__device__ int   g_active[Bsz];
__device__ float g_scores[Bsz];
__device__ int   g_exitl[Bsz];

// ---------------- helpers ----------------------------------------------------
__device__ __forceinline__ float blockReduceSum128(float val, float* smem4) {
    int lane = threadIdx.x & 31, warp = threadIdx.x >> 5;
    #pragma unroll
    for (int o = 16; o > 0; o >>= 1) val += __shfl_down_sync(0xffffffffu, val, o);
    if (lane == 0) smem4[warp] = val;
    __syncthreads();
    float v = (threadIdx.x < 4) ? smem4[threadIdx.x] : 0.f;
    if (warp == 0) {
        v += __shfl_down_sync(0xffffffffu, v, 2);
        v += __shfl_down_sync(0xffffffffu, v, 1);
        if (lane == 0) smem4[0] = v;
    }
    __syncthreads();
    float r = smem4[0];
    __syncthreads();
    return r;
}

__device__ __forceinline__ void cpasync16(void* dst, const void* src) {
    unsigned sa = (unsigned)__cvta_generic_to_shared(dst);
    asm volatile("cp.async.cg.shared.global [%0], [%1], 16;\n" :: "r"(sa), "l"(src));
}
__device__ __forceinline__ void cp_commit() { asm volatile("cp.async.commit_group;\n"); }
__device__ __forceinline__ void cp_wait0()  { asm volatile("cp.async.wait_group 0;\n"); }

__device__ __forceinline__ float tf32r(float x) {   // round-to-nearest tf32
    unsigned u;
    asm("cvt.rna.tf32.f32 %0, %1;" : "=r"(u) : "f"(x));
    return __uint_as_float(u);
}

#define MMA_TF32(d, a, bfr) \
    asm volatile("mma.sync.aligned.m16n8k8.row.col.f32.tf32.tf32.f32 " \
        "{%0,%1,%2,%3}, {%4,%5,%6,%7}, {%8,%9}, {%0,%1,%2,%3};" \
        : "+f"((d)[0]), "+f"((d)[1]), "+f"((d)[2]), "+f"((d)[3]) \
        : "r"((a)[0]), "r"((a)[1]), "r"((a)[2]), "r"((a)[3]), \
          "r"((bfr)[0]), "r"((bfr)[1]))

// ---------------- state init -------------------------------------------------
__global__ void init_state_kernel() {
    int t = threadIdx.x;
    if (t < Bsz) { g_active[t] = 1; g_scores[t] = 0.f; g_exitl[t] = 0; }
}

// ---------------- embeddings + LN --------------------------------------------
__global__ void embed_ln_kernel(const int* __restrict__ ids, const int* __restrict__ tts,
                                const float* __restrict__ we, const float* __restrict__ pe,
                                const float* __restrict__ te, const float* __restrict__ g,
                                const float* __restrict__ b) {
    __shared__ float red[4];
    int row = blockIdx.x, s = row & (Ssz - 1), tid = threadIdx.x;
    int id = ids[row], tt = tts[row];
    float x[3];
    #pragma unroll
    for (int i = 0; i < 3; i++) {
        int j = tid + i * 128;
        x[i] = we[id * Hsz + j] + pe[s * Hsz + j] + te[tt * Hsz + j];
    }
    float mean = blockReduceSum128(x[0] + x[1] + x[2], red) * (1.f / Hsz);
    float sq = 0.f;
    #pragma unroll
    for (int i = 0; i < 3; i++) { float d = x[i] - mean; sq += d * d; }
    float var = blockReduceSum128(sq, red) * (1.f / Hsz);
    float inv = rsqrtf(var + 1e-12f);
    #pragma unroll
    for (int i = 0; i < 3; i++) {
        int j = tid + i * 128;
        g_h[row * Hsz + j] = g[j] * (x[i] - mean) * inv + b[j];
    }
}

// ---------------- TF32 tensor-core GEMM (128x128 block, 64x64 warp tile) -----
// C[MxN] = A[MxK] @ W[KxN] + bias, optional exact GELU.
// 4 warps as 2(m) x 2(n). 128 threads. BK=16. cp.async double-buffered.
// Static smem (37.9KB) -> 2 CTAs/SM. A smem [m][20], B smem [k][136].
struct TgemmSmem {
    float As[2][128][20];
    float Bs[2][16][136];
};

__device__ __forceinline__ void tgemm_body(
        const float* __restrict__ A, const float* __restrict__ W,
        const float* __restrict__ bias, float* __restrict__ C,
        int N, int K, int act, int bx, int by, TgemmSmem& sm) {
    const int t = threadIdx.x;     // 128 threads
    const int lane = t & 31, warp = t >> 5;
    const int kk = lane & 3, r = lane >> 2;
    const int mw = (warp >> 1) * 64;       // 2 m-warps
    const int nw = (warp & 1) * 64;        // 2 n-warps
    const int br = by * 128, bc = bx * 128;

    // global load indexing (128 threads)
    const int arow = t >> 2, ac4 = (t & 3) * 4;    // A: 32 rows/pass x 16 cols
    const int brow = t >> 5, bc4 = (t & 31) * 4;   // B: 4 rows/pass x 128 cols
    const float* Ag0 = A + (size_t)(br + arow) * K + ac4;
    const float* Ag1 = Ag0 + (size_t)32 * K;
    const float* Ag2 = Ag0 + (size_t)64 * K;
    const float* Ag3 = Ag0 + (size_t)96 * K;
    const float* Wg0 = W + (size_t)brow * N + bc + bc4;
    const float* Wg1 = Wg0 + (size_t)4 * N;
    const float* Wg2 = Wg0 + (size_t)8 * N;
    const float* Wg3 = Wg0 + (size_t)12 * N;

    float acc[4][8][4] = {};

    const int T = K >> 4;
    cpasync16(&sm.As[0][arow][ac4], Ag0);
    cpasync16(&sm.As[0][arow + 32][ac4], Ag1);
    cpasync16(&sm.As[0][arow + 64][ac4], Ag2);
    cpasync16(&sm.As[0][arow + 96][ac4], Ag3);
    cpasync16(&sm.Bs[0][brow][bc4], Wg0);
    cpasync16(&sm.Bs[0][brow + 4][bc4], Wg1);
    cpasync16(&sm.Bs[0][brow + 8][bc4], Wg2);
    cpasync16(&sm.Bs[0][brow + 12][bc4], Wg3);
    cp_commit();

    int buf = 0;
    for (int tt = 0; tt < T; tt++) {
        cp_wait0();
        __syncthreads();
        if (tt + 1 < T) {
            int k0 = (tt + 1) << 4;
            int nb = buf ^ 1;
            cpasync16(&sm.As[nb][arow][ac4], Ag0 + k0);
            cpasync16(&sm.As[nb][arow + 32][ac4], Ag1 + k0);
            cpasync16(&sm.As[nb][arow + 64][ac4], Ag2 + k0);
            cpasync16(&sm.As[nb][arow + 96][ac4], Ag3 + k0);
            cpasync16(&sm.Bs[nb][brow][bc4], Wg0 + (size_t)k0 * N);
            cpasync16(&sm.Bs[nb][brow + 4][bc4], Wg1 + (size_t)k0 * N);
            cpasync16(&sm.Bs[nb][brow + 8][bc4], Wg2 + (size_t)k0 * N);
            cpasync16(&sm.Bs[nb][brow + 12][bc4], Wg3 + (size_t)k0 * N);
            cp_commit();
        }
        #pragma unroll
        for (int ks = 0; ks < 16; ks += 8) {
            unsigned a[4][4], b[8][2];
            #pragma unroll
            for (int mt = 0; mt < 4; mt++) {
                int m = mw + mt * 16 + r;
                a[mt][0] = __float_as_uint(sm.As[buf][m][ks + kk]);
                a[mt][1] = __float_as_uint(sm.As[buf][m + 8][ks + kk]);
                a[mt][2] = __float_as_uint(sm.As[buf][m][ks + 4 + kk]);
                a[mt][3] = __float_as_uint(sm.As[buf][m + 8][ks + 4 + kk]);
            }
            #pragma unroll
            for (int nt = 0; nt < 8; nt++) {
                int n = nw + nt * 8 + r;
                b[nt][0] = __float_as_uint(sm.Bs[buf][ks + kk][n]);
                b[nt][1] = __float_as_uint(sm.Bs[buf][ks + 4 + kk][n]);
            }
            #pragma unroll
            for (int mt = 0; mt < 4; mt++)
                #pragma unroll
                for (int nt = 0; nt < 8; nt++)
                    MMA_TF32(acc[mt][nt], a[mt], b[nt]);
        }
        __syncthreads();
        buf ^= 1;
    }

    #pragma unroll
    for (int nt = 0; nt < 8; nt++) {
        int col = bc + nw + nt * 8 + 2 * kk;
        float b0 = bias[col], b1 = bias[col + 1];
        #pragma unroll
        for (int mt = 0; mt < 4; mt++) {
            int row = br + mw + mt * 16 + r;
            float v0 = acc[mt][nt][0] + b0, v1 = acc[mt][nt][1] + b1;
            float v2 = acc[mt][nt][2] + b0, v3 = acc[mt][nt][3] + b1;
            if (act == 1) {
                v0 = 0.5f * v0 * (1.f + erff(v0 * 0.70710678118654752f));
                v1 = 0.5f * v1 * (1.f + erff(v1 * 0.70710678118654752f));
                v2 = 0.5f * v2 * (1.f + erff(v2 * 0.70710678118654752f));
                v3 = 0.5f * v3 * (1.f + erff(v3 * 0.70710678118654752f));
            }
            *reinterpret_cast<float2*>(&C[(size_t)row * N + col]) = make_float2(v0, v1);
            *reinterpret_cast<float2*>(&C[(size_t)(row + 8) * N + col]) = make_float2(v2, v3);
        }
    }
}

__global__ __launch_bounds__(128, 2) void tgemm_kernel(
        const float* __restrict__ A, const float* __restrict__ W,
        const float* __restrict__ bias, float* __restrict__ C,
        int N, int K, int act) {
    __shared__ TgemmSmem sm;
    tgemm_body(A, W, bias, C, N, K, act, blockIdx.x, blockIdx.y, sm);
}

__global__ __launch_bounds__(128, 2) void tgemm_qkv_kernel(
        const float* __restrict__ A,
        const float* __restrict__ Wq, const float* __restrict__ Wk, const float* __restrict__ Wv,
        const float* __restrict__ bq, const float* __restrict__ bk, const float* __restrict__ bv,
        float* __restrict__ Cq, float* __restrict__ Ck, float* __restrict__ Cv) {
    __shared__ TgemmSmem sm;
    const float* Ws[3] = {Wq, Wk, Wv};
    const float* bs[3] = {bq, bk, bv};
    float* Cs[3] = {Cq, Ck, Cv};
    int z = blockIdx.z;
    tgemm_body(A, Ws[z], bs[z], Cs[z], Hsz, Hsz, 0, blockIdx.x, blockIdx.y, sm);
}

// ---------------- tensor-core flash attention (unchanged from R5 winner) -----
#define ATTN_SMEM_FLOATS (256*36 + 32*260 + 8*32*36 + 256)
#define ATTN_SMEM_BYTES  (ATTN_SMEM_FLOATS * 4)
#define SCL 0.17677669529663688f

__global__ __launch_bounds__(256, 2) void attn_mma_kernel(
        const float* __restrict__ q, const float* __restrict__ k,
        const float* __restrict__ v, const int* __restrict__ mask,
        float* __restrict__ ctx) {
    extern __shared__ float sm[];
    float* Ks = sm;                     // [256][36]
    float* Vt = sm + 256*36;            // [32][260]
    float* Pw = Vt + 32*260;            // [8][32][36]
    float* bi = Pw + 8*32*36;           // [256]

    const int h = blockIdx.x, b = blockIdx.y;
    const int tid = threadIdx.x, lane = tid & 31, w = tid >> 5;
    const int gr = lane >> 2, kk = lane & 3;

    for (int idx = tid; idx < 256*32; idx += 256) {
        int key = idx >> 5, d = idx & 31;
        size_t gi = (size_t)(b*Ssz + key)*Hsz + h*DHs + d;
        Ks[key*36 + d] = tf32r(k[gi]);
        Vt[d*260 + key] = tf32r(v[gi]);
    }
    bi[tid] = (1.f - (float)mask[b*Ssz + tid]) * -1e9f;
    __syncthreads();

    unsigned aq[2][4][4];
    const int qrow0 = b*Ssz + w*32 + gr;
    #pragma unroll
    for (int mt = 0; mt < 2; mt++)
        #pragma unroll
        for (int kt = 0; kt < 4; kt++) {
            const float* qp = q + (size_t)(qrow0 + mt*16)*Hsz + h*DHs + kt*8 + kk;
            aq[mt][kt][0] = __float_as_uint(tf32r(qp[0]));
            aq[mt][kt][1] = __float_as_uint(tf32r(qp[8*(size_t)Hsz]));
            aq[mt][kt][2] = __float_as_uint(tf32r(qp[4]));
            aq[mt][kt][3] = __float_as_uint(tf32r(qp[8*(size_t)Hsz + 4]));
        }

    float m_[2][2] = {{-1e30f, -1e30f}, {-1e30f, -1e30f}};
    float l_[2][2] = {};
    float o[2][4][4] = {};
    float* pw = Pw + w*(32*36);

    for (int t = 0; t < 8; t++) {
        const int kb = t*32;
        float s[2][4][4] = {};
        #pragma unroll
        for (int kt = 0; kt < 4; kt++) {
            unsigned bf[4][2];
            #pragma unroll
            for (int nt = 0; nt < 4; nt++) {
                const float* kp = &Ks[(kb + nt*8 + gr)*36 + kt*8 + kk];
                bf[nt][0] = __float_as_uint(kp[0]);
                bf[nt][1] = __float_as_uint(kp[4]);
            }
            #pragma unroll
            for (int mt = 0; mt < 2; mt++)
                #pragma unroll
                for (int nt = 0; nt < 4; nt++)
                    MMA_TF32(s[mt][nt], aq[mt][kt], bf[nt]);
        }
        #pragma unroll
        for (int nt = 0; nt < 4; nt++) {
            float2 bv = *reinterpret_cast<const float2*>(&bi[kb + nt*8 + 2*kk]);
            #pragma unroll
            for (int mt = 0; mt < 2; mt++) {
                s[mt][nt][0] = s[mt][nt][0]*SCL + bv.x;
                s[mt][nt][1] = s[mt][nt][1]*SCL + bv.y;
                s[mt][nt][2] = s[mt][nt][2]*SCL + bv.x;
                s[mt][nt][3] = s[mt][nt][3]*SCL + bv.y;
            }
        }
        #pragma unroll
        for (int mt = 0; mt < 2; mt++) {
            #pragma unroll
            for (int hf = 0; hf < 2; hf++) {
                float tm = -1e30f;
                #pragma unroll
                for (int nt = 0; nt < 4; nt++)
                    tm = fmaxf(tm, fmaxf(s[mt][nt][2*hf], s[mt][nt][2*hf+1]));
                tm = fmaxf(tm, __shfl_xor_sync(0xffffffffu, tm, 1));
                tm = fmaxf(tm, __shfl_xor_sync(0xffffffffu, tm, 2));
                float nm = fmaxf(m_[mt][hf], tm);
                float corr = __expf(m_[mt][hf] - nm);
                m_[mt][hf] = nm;
                float rs = 0.f;
                #pragma unroll
                for (int nt = 0; nt < 4; nt++) {
                    float p0 = __expf(s[mt][nt][2*hf] - nm);
                    float p1 = __expf(s[mt][nt][2*hf+1] - nm);
                    s[mt][nt][2*hf] = p0; s[mt][nt][2*hf+1] = p1;
                    rs += p0 + p1;
                    o[mt][nt][2*hf]   *= corr;
                    o[mt][nt][2*hf+1] *= corr;
                }
                rs += __shfl_xor_sync(0xffffffffu, rs, 1);
                rs += __shfl_xor_sync(0xffffffffu, rs, 2);
                l_[mt][hf] = l_[mt][hf]*corr + rs;
            }
        }
        #pragma unroll
        for (int mt = 0; mt < 2; mt++)
            #pragma unroll
            for (int nt = 0; nt < 4; nt++) {
                *reinterpret_cast<float2*>(&pw[(mt*16+gr)*36 + nt*8 + 2*kk]) =
                    make_float2(s[mt][nt][0], s[mt][nt][1]);
                *reinterpret_cast<float2*>(&pw[(mt*16+gr+8)*36 + nt*8 + 2*kk]) =
                    make_float2(s[mt][nt][2], s[mt][nt][3]);
            }
        __syncwarp();
        #pragma unroll
        for (int kt = 0; kt < 4; kt++) {
            unsigned ap[2][4];
            #pragma unroll
            for (int mt = 0; mt < 2; mt++) {
                ap[mt][0] = __float_as_uint(pw[(mt*16+gr)*36 + kt*8 + kk]);
                ap[mt][1] = __float_as_uint(pw[(mt*16+gr+8)*36 + kt*8 + kk]);
                ap[mt][2] = __float_as_uint(pw[(mt*16+gr)*36 + kt*8 + kk + 4]);
                ap[mt][3] = __float_as_uint(pw[(mt*16+gr+8)*36 + kt*8 + kk + 4]);
            }
            unsigned bf[4][2];
            #pragma unroll
            for (int nt = 0; nt < 4; nt++) {
                const float* vp = &Vt[(nt*8+gr)*260 + kb + kt*8 + kk];
                bf[nt][0] = __float_as_uint(vp[0]);
                bf[nt][1] = __float_as_uint(vp[4]);
            }
            #pragma unroll
            for (int mt = 0; mt < 2; mt++)
                #pragma unroll
                for (int nt = 0; nt < 4; nt++)
                    MMA_TF32(o[mt][nt], ap[mt], bf[nt]);
        }
        __syncwarp();
    }

    #pragma unroll
    for (int mt = 0; mt < 2; mt++) {
        float i0 = 1.f / l_[mt][0], i1 = 1.f / l_[mt][1];
        #pragma unroll
        for (int nt = 0; nt < 4; nt++) {
            size_t base = (size_t)(qrow0 + mt*16)*Hsz + h*DHs + nt*8 + 2*kk;
            *reinterpret_cast<float2*>(&ctx[base]) =
                make_float2(o[mt][nt][0]*i0, o[mt][nt][1]*i0);
            *reinterpret_cast<float2*>(&ctx[base + 8*(size_t)Hsz]) =
                make_float2(o[mt][nt][2]*i1, o[mt][nt][3]*i1);
        }
    }
}

// ---------------- residual + LN (warp per row, float4) ------------------------
__global__ __launch_bounds__(256) void residual_ln_kernel(
        const float* __restrict__ delta,
        const float* __restrict__ g, const float* __restrict__ b) {
    const int lane = threadIdx.x & 31, w = threadIdx.x >> 5;
    const int row = blockIdx.x * 8 + w;
    const float4* hp = reinterpret_cast<const float4*>(g_h + (size_t)row * Hsz);
    const float4* dp = reinterpret_cast<const float4*>(delta + (size_t)row * Hsz);
    float4 x[3];
    float sum = 0.f;
    #pragma unroll
    for (int i = 0; i < 3; i++) {
        float4 hv = hp[lane + i * 32], dv = dp[lane + i * 32];
        x[i] = make_float4(hv.x + dv.x, hv.y + dv.y, hv.z + dv.z, hv.w + dv.w);
        sum += x[i].x + x[i].y + x[i].z + x[i].w;
    }
    #pragma unroll
    for (int o = 16; o > 0; o >>= 1) sum += __shfl_xor_sync(0xffffffffu, sum, o);
    float mean = sum * (1.f / Hsz);
    float sq = 0.f;
    #pragma unroll
    for (int i = 0; i < 3; i++) {
        float dx = x[i].x - mean, dy = x[i].y - mean, dz = x[i].z - mean, dw = x[i].w - mean;
        sq += dx*dx + dy*dy + dz*dz + dw*dw;
    }
    #pragma unroll
    for (int o = 16; o > 0; o >>= 1) sq += __shfl_xor_sync(0xffffffffu, sq, o);
    float inv = rsqrtf(sq * (1.f / Hsz) + 1e-12f);
    float4* op = reinterpret_cast<float4*>(g_h + (size_t)row * Hsz);
    const float4* gp = reinterpret_cast<const float4*>(g);
    const float4* bp = reinterpret_cast<const float4*>(b);
    #pragma unroll
    for (int i = 0; i < 3; i++) {
        int j = lane + i * 32;
        float4 gv = gp[j], bv = bp[j];
        op[j] = make_float4(gv.x * (x[i].x - mean) * inv + bv.x,
                            gv.y * (x[i].y - mean) * inv + bv.y,
                            gv.z * (x[i].z - mean) * inv + bv.z,
                            gv.w * (x[i].w - mean) * inv + bv.w);
    }
}

// ---------------- offramp: entropy decision on CLS token ---------------------
__global__ void offramp_kernel(const float* __restrict__ Wr, const float* __restrict__ br,
                               int layer) {
    __shared__ float w[Hsz];
    int tid = threadIdx.x;  // 128
    #pragma unroll
    for (int i = 0; i < 3; i++) w[tid + i * 128] = Wr[layer * Hsz + tid + i * 128];
    __syncthreads();
    int b = tid;
    const float* hr = g_h + (size_t)(b * Ssz) * Hsz;
    float l = br[layer];
    for (int kk = 0; kk < Hsz; kk++) l = fmaf(hr[kk], w[kk], l);
    float lsp = (l > 0.f) ? -log1pf(expf(-l)) : (l - log1pf(expf(l)));
    float lsn = (l < 0.f) ? -log1pf(expf(l)) : (-l - log1pf(expf(-l)));
    float p = 1.f / (1.f + expf(-l));
    float ent = -(p * lsp + (1.f - p) * lsn);
    if (g_active[b] && ent < 0.1f) {
        g_scores[b] = l; g_exitl[b] = layer; g_active[b] = 0;
    }
}

// ---------------- pooler -----------------------------------------------------
__global__ void pooler_kernel(const float* __restrict__ Wp, const float* __restrict__ bp) {
    __shared__ float hr[Hsz];
    int b = blockIdx.x, tid = threadIdx.x;   // 384 threads
    hr[tid] = g_h[(size_t)(b * Ssz) * Hsz + tid];
    __syncthreads();
    float acc = bp[tid];
    for (int kk = 0; kk < Hsz; kk++) acc = fmaf(hr[kk], Wp[kk * Hsz + tid], acc);
    g_pooled[b * Hsz + tid] = tanhf(acc);
}

// ---------------- final classifier + output assembly -------------------------
__global__ void final_kernel(const float* __restrict__ Wc, const float* __restrict__ bc,
                             float* __restrict__ out, int out_size) {
    __shared__ int counts[8];
    int tid = threadIdx.x;  // 128
    if (tid < 8) counts[tid] = 0;
    __syncthreads();
    int b = tid;
    float acc = bc[0];
    for (int kk = 0; kk < Hsz; kk++) acc = fmaf(g_pooled[b * Hsz + kk], Wc[kk], acc);
    float sc; int el;
    if (g_active[b]) { sc = acc; el = NOFF; }
    else             { sc = g_scores[b]; el = g_exitl[b]; }
    atomicAdd(&counts[el], 1);
    __syncthreads();
    out[b] = sc;
    out[Bsz + b] = (float)el;
    if (tid < NOFF + 1) out[2 * Bsz + tid] = (float)counts[tid];
    for (int i = 2 * Bsz + NOFF + 1 + tid; i < out_size; i += 128) out[i] = 0.f;
}

// ---------------- launch -----------------------------------------------------
extern "C" void kernel_launch(void* const* d_in, const int* in_sizes, int n_in,
                              void* d_out, int out_size) {
    (void)in_sizes; (void)n_in;
    const int*   input_ids      = (const int*)d_in[0];
    const int*   attention_mask = (const int*)d_in[1];
    const int*   token_type_ids = (const int*)d_in[2];
    const float* word_emb = (const float*)d_in[3];
    const float* pos_emb  = (const float*)d_in[4];
    const float* type_emb = (const float*)d_in[5];
    const float* emb_ln_g = (const float*)d_in[6];
    const float* emb_ln_b = (const float*)d_in[7];
    const float* Wq = (const float*)d_in[8];  const float* bq = (const float*)d_in[9];
    const float* Wk = (const float*)d_in[10]; const float* bk = (const float*)d_in[11];
    const float* Wv = (const float*)d_in[12]; const float* bv = (const float*)d_in[13];
    const float* Wo = (const float*)d_in[14]; const float* bo = (const float*)d_in[15];
    const float* ln1_g = (const float*)d_in[16]; const float* ln1_b = (const float*)d_in[17];
    const float* Wi = (const float*)d_in[18]; const float* bi = (const float*)d_in[19];
    const float* Wfo = (const float*)d_in[20]; const float* bfo = (const float*)d_in[21];
    const float* ln2_g = (const float*)d_in[22]; const float* ln2_b = (const float*)d_in[23];
    const float* Wp = (const float*)d_in[24]; const float* bp = (const float*)d_in[25];
    const float* Wc = (const float*)d_in[26]; const float* bc = (const float*)d_in[27];
    const float* Wr = (const float*)d_in[28]; const float* br = (const float*)d_in[29];

    float *hp, *qp, *kp, *vp, *cp, *tp, *fp;
    cudaGetSymbolAddress((void**)&hp, g_h);
    cudaGetSymbolAddress((void**)&qp, g_q);
    cudaGetSymbolAddress((void**)&kp, g_k);
    cudaGetSymbolAddress((void**)&vp, g_v);
    cudaGetSymbolAddress((void**)&cp, g_ctx);
    cudaGetSymbolAddress((void**)&tp, g_tmp);
    cudaGetSymbolAddress((void**)&fp, g_ff);

    cudaFuncSetAttribute(attn_mma_kernel,
                         cudaFuncAttributeMaxDynamicSharedMemorySize, ATTN_SMEM_BYTES);

    init_state_kernel<<<1, 128>>>();
    embed_ln_kernel<<<ROWS, 128>>>(input_ids, token_type_ids, word_emb, pos_emb, type_emb,
                                   emb_ln_g, emb_ln_b);

    dim3 gHH(Hsz / 128, ROWS / 128);          // (3, 256)
    dim3 gQKV(Hsz / 128, ROWS / 128, 3);      // (3, 256, 3)
    dim3 gHF(Fsz / 128, ROWS / 128);          // (12, 256)

    for (int i = 0; i < Lyr; i++) {
        const float* wq = Wq + (size_t)i * Hsz * Hsz;
        const float* wk = Wk + (size_t)i * Hsz * Hsz;
        const float* wv = Wv + (size_t)i * Hsz * Hsz;
        const float* wo = Wo + (size_t)i * Hsz * Hsz;
        tgemm_qkv_kernel<<<gQKV, 128>>>(hp, wq, wk, wv,
                                        bq + i * Hsz, bk + i * Hsz, bv + i * Hsz,
                                        qp, kp, vp);
        attn_mma_kernel<<<dim3(NHs, Bsz), 256, ATTN_SMEM_BYTES>>>(qp, kp, vp,
                                                                  attention_mask, cp);
        tgemm_kernel<<<gHH, 128>>>(cp, wo, bo + i * Hsz, tp, Hsz, Hsz, 0);
        residual_ln_kernel<<<ROWS / 8, 256>>>(tp, ln1_g + i * Hsz, ln1_b + i * Hsz);
        tgemm_kernel<<<gHF, 128>>>(hp, Wi + (size_t)i * Hsz * Fsz, bi + i * Fsz, fp,
                                   Fsz, Hsz, 1);
        tgemm_kernel<<<gHH, 128>>>(fp, Wfo + (size_t)i * Fsz * Hsz, bfo + i * Hsz, tp,
                                   Hsz, Fsz, 0);
        residual_ln_kernel<<<ROWS / 8, 256>>>(tp, ln2_g + i * Hsz, ln2_b + i * Hsz);
        if (i < NOFF) {
            offramp_kernel<<<1, 128>>>(Wr, br, i);
        }
    }
    pooler_kernel<<<Bsz, Hsz>>>(Wp, bp);
    final_kernel<<<1, 128>>>(Wc, bc, (float*)d_out, out_size);
}